// round 1
// baseline (speedup 1.0000x reference)
#include <cuda_runtime.h>
#include <math.h>

#define NTOK 64
#define DIM 512
#define HEADS 8
#define HD 64
#define NB 2048
#define MROWS (NB * NTOK)   // 131072
#define SCALE 0.125f        // 64^-0.5

// ---------------- scratch (device globals; no allocation) ----------------
static __device__ float g_qkv[(size_t)MROWS * 1536];   // [M,1536]: q(scaled)|k|v
static __device__ float g_mult[(size_t)NB * NTOK * NTOK];
static __device__ float g_o[(size_t)MROWS * DIM];

// =====================================================================
// SGEMM:  C[m*ldc + n] = alpha * ( sum_k A[m*K+k]*B[n*K+k] + bias[n] )
// 128x128 block tile, BK=8, 256 threads, 8x8 per thread (2x2 of 4x4)
// =====================================================================
__global__ __launch_bounds__(256, 2)
void sgemm_nt(const float* __restrict__ A, const float* __restrict__ B,
              const float* __restrict__ bias, float* __restrict__ C,
              int K, long ldc, float alpha)
{
    __shared__ float As[8][128];
    __shared__ float Bs[8][128];
    const int tid = threadIdx.x;
    const int tx = tid & 15, ty = tid >> 4;
    const long m0 = (long)blockIdx.y * 128;
    const long n0 = (long)blockIdx.x * 128;
    const int srow = (tid & 1) << 2;   // k offset 0 or 4 within tile
    const int scol = tid >> 1;         // 0..127
    const float* Ag = A + (m0 + scol) * (long)K + srow;
    const float* Bg = B + (n0 + scol) * (long)K + srow;

    float acc[8][8];
#pragma unroll
    for (int i = 0; i < 8; i++)
#pragma unroll
        for (int j = 0; j < 8; j++) acc[i][j] = 0.f;

    float4 an = *(const float4*)(Ag);
    float4 bn = *(const float4*)(Bg);

    for (int k0 = 0; k0 < K; k0 += 8) {
        As[srow + 0][scol] = an.x; As[srow + 1][scol] = an.y;
        As[srow + 2][scol] = an.z; As[srow + 3][scol] = an.w;
        Bs[srow + 0][scol] = bn.x; Bs[srow + 1][scol] = bn.y;
        Bs[srow + 2][scol] = bn.z; Bs[srow + 3][scol] = bn.w;
        __syncthreads();
        if (k0 + 8 < K) {
            an = *(const float4*)(Ag + k0 + 8);
            bn = *(const float4*)(Bg + k0 + 8);
        }
#pragma unroll
        for (int kk = 0; kk < 8; kk++) {
            float a[8], b[8];
            *(float4*)(a)     = *(const float4*)&As[kk][ty * 4];
            *(float4*)(a + 4) = *(const float4*)&As[kk][64 + ty * 4];
            *(float4*)(b)     = *(const float4*)&Bs[kk][tx * 4];
            *(float4*)(b + 4) = *(const float4*)&Bs[kk][64 + tx * 4];
#pragma unroll
            for (int i = 0; i < 8; i++)
#pragma unroll
                for (int j = 0; j < 8; j++)
                    acc[i][j] += a[i] * b[j];
        }
        __syncthreads();
    }

#pragma unroll
    for (int ih = 0; ih < 2; ih++)
#pragma unroll
        for (int i = 0; i < 4; i++) {
            long m = m0 + ih * 64 + ty * 4 + i;
#pragma unroll
            for (int jh = 0; jh < 2; jh++) {
                long n = n0 + jh * 64 + tx * 4;
                float4 bv = *(const float4*)(bias + n);
                float4 o;
                o.x = alpha * (acc[ih * 4 + i][jh * 4 + 0] + bv.x);
                o.y = alpha * (acc[ih * 4 + i][jh * 4 + 1] + bv.y);
                o.z = alpha * (acc[ih * 4 + i][jh * 4 + 2] + bv.z);
                o.w = alpha * (acc[ih * 4 + i][jh * 4 + 3] + bv.w);
                *(float4*)(C + m * ldc + n) = o;
            }
        }
}

// =====================================================================
// Correlation-map kernel: one block per window, mult[b][i][j]
// =====================================================================
#define SMEM_MULT_FLOATS (384*64 + 16*64 + 64 + 64 + 192 + 192 + 64 + 512)

__global__ __launch_bounds__(256)
void mult_kernel(const float* __restrict__ dino, const float* __restrict__ point,
                 const float* __restrict__ sdf, const float* __restrict__ normal,
                 const float* __restrict__ smask, const float* __restrict__ cmask,
                 float* __restrict__ mout)
{
    extern __shared__ float sm[];
    float* sDT   = sm;               // [384][64] dino transposed
    float* sST   = sDT + 384 * 64;   // [16][64]  sdf transposed
    float* rnD   = sST + 16 * 64;    // [64]
    float* rnS   = rnD + 64;         // [64]
    float* sp    = rnS + 64;         // [64][3]
    float* sn    = sp + 192;         // [64][3]
    float* scode = sn + 192;         // [64]
    float* scl   = scode + 64;       // [64][8]

    const int b = blockIdx.x;
    const int tid = threadIdx.x;

    // dino -> smem transposed
    const float* dg = dino + (size_t)b * 64 * 384;
    for (int idx = tid; idx < 64 * 96; idx += 256) {
        int row = idx / 96;
        int kg = (idx % 96) * 4;
        float4 v = *(const float4*)(dg + row * 384 + kg);
        sDT[(kg + 0) * 64 + row] = v.x;
        sDT[(kg + 1) * 64 + row] = v.y;
        sDT[(kg + 2) * 64 + row] = v.z;
        sDT[(kg + 3) * 64 + row] = v.w;
    }
    // sdf -> smem transposed
    const float* sg = sdf + (size_t)b * 64 * 16;
    if (tid < 256) {
        int idx = tid;
        if (idx < 256) {
            int row = idx >> 2;
            int kg = (idx & 3) * 4;
            float4 v = *(const float4*)(sg + row * 16 + kg);
            sST[(kg + 0) * 64 + row] = v.x;
            sST[(kg + 1) * 64 + row] = v.y;
            sST[(kg + 2) * 64 + row] = v.z;
            sST[(kg + 3) * 64 + row] = v.w;
        }
    }
    if (tid < 192) {
        sp[tid] = point[(size_t)b * 192 + tid];
        sn[tid] = normal[(size_t)b * 192 + tid];
    }
    if (tid < 64)
        scode[tid] = (smask[(size_t)b * 64 + tid] < 0.1f) ? 1.f : 2.f;
    for (int idx = tid; idx < 512; idx += 256)
        scl[idx] = cmask[(size_t)b * 512 + idx];
    __syncthreads();

    if (tid < 64) {
        float s = 0.f;
        for (int k = 0; k < 384; k++) { float v = sDT[k * 64 + tid]; s += v * v; }
        float nn = fminf(fmaxf(sqrtf(s), 1e-20f), 1e10f);
        rnD[tid] = 1.0f / nn;
        float s2 = 0.f;
        for (int k = 0; k < 16; k++) { float v = sST[k * 64 + tid]; s2 += v * v; }
        nn = fminf(fmaxf(sqrtf(s2), 1e-20f), 1e10f);
        rnS[tid] = 1.0f / nn;
    }
    __syncthreads();

    const int tx = tid & 15, ty = tid >> 4;
    float dacc[4][4], sacc[4][4];
#pragma unroll
    for (int i = 0; i < 4; i++)
#pragma unroll
        for (int j = 0; j < 4; j++) { dacc[i][j] = 0.f; sacc[i][j] = 0.f; }

#pragma unroll 4
    for (int k = 0; k < 384; k++) {
        float4 a4 = *(const float4*)&sDT[k * 64 + ty * 4];
        float4 b4 = *(const float4*)&sDT[k * 64 + tx * 4];
        float a[4] = {a4.x, a4.y, a4.z, a4.w};
        float b[4] = {b4.x, b4.y, b4.z, b4.w};
#pragma unroll
        for (int i = 0; i < 4; i++)
#pragma unroll
            for (int j = 0; j < 4; j++)
                dacc[i][j] += a[i] * b[j];
    }
#pragma unroll
    for (int k = 0; k < 16; k++) {
        float4 a4 = *(const float4*)&sST[k * 64 + ty * 4];
        float4 b4 = *(const float4*)&sST[k * 64 + tx * 4];
        float a[4] = {a4.x, a4.y, a4.z, a4.w};
        float b[4] = {b4.x, b4.y, b4.z, b4.w};
#pragma unroll
        for (int i = 0; i < 4; i++)
#pragma unroll
            for (int j = 0; j < 4; j++)
                sacc[i][j] += a[i] * b[j];
    }

    float* mrow = mout + (size_t)b * 4096;
#pragma unroll
    for (int i = 0; i < 4; i++) {
        int I = ty * 4 + i;
        float res[4];
#pragma unroll
        for (int j = 0; j < 4; j++) {
            int J = tx * 4 + j;
            float dmap = fminf(fmaxf(dacc[i][j] * rnD[I] * rnD[J], 0.f), 1e10f);
            float smap = 1.f - fminf(fmaxf(sacc[i][j] * rnS[I] * rnS[J], 0.f), 1.f);
            float P1 = 0.f, P2 = 0.f;
#pragma unroll
            for (int d = 0; d < 3; d++) {
                float diff = sp[I * 3 + d] - sp[J * 3 + d];
                P1 += diff * sn[I * 3 + d];
                P2 += diff * sn[J * 3 + d];
            }
            float plane = expf(-0.5f * (fabsf(P1) + fabsf(P2)));
            float mm = (scode[I] * scode[J] == 2.f) ? 1.f : 0.2f;
            float cc = 0.f;
#pragma unroll
            for (int c = 0; c < 8; c++) cc += scl[I * 8 + c] * scl[J * 8 + c];
            res[j] = dmap * smap * plane * cc * mm;
        }
        *(float4*)(mrow + I * 64 + tx * 4) = make_float4(res[0], res[1], res[2], res[3]);
    }
}

// =====================================================================
// Attention kernel: one block per window, loops over 8 heads
// =====================================================================
#define SMEM_ATTN_FLOATS (64*64 + 64*68 + 64*64 + 64*64 + 225*8)

__global__ __launch_bounds__(256)
void attn_kernel(const float* __restrict__ mult, const float* __restrict__ rel_table,
                 const float* __restrict__ qkv, float* __restrict__ obuf)
{
    extern __shared__ float sm[];
    float* qN    = sm;               // [64][64]   q natural
    float* kT    = qN + 64 * 64;     // [64][68]   k transposed (d-major); later v natural (stride 68)
    float* sS    = kT + 64 * 68;     // [64][64]   logits / probs
    float* sMult = sS + 64 * 64;     // [64][64]
    float* sBias = sMult + 64 * 64;  // [225*8]

    const int b = blockIdx.x;
    const int tid = threadIdx.x;
    const int tx = tid & 15, ty = tid >> 4;
    const int lane = tid & 31, warp = tid >> 5;

    for (int i = tid; i < 1024; i += 256)
        ((float4*)sMult)[i] = ((const float4*)(mult + (size_t)b * 4096))[i];
    for (int i = tid; i < 1800; i += 256)
        sBias[i] = rel_table[i];

    const float* qbase = qkv + (size_t)(b * 64) * 1536;

    for (int h = 0; h < HEADS; h++) {
        // load q (natural) and k (transposed)
        for (int idx = tid; idx < 1024; idx += 256) {
            int row = idx >> 4;
            int dg = (idx & 15) << 2;
            float4 qv = *(const float4*)(qbase + (size_t)row * 1536 + h * 64 + dg);
            *(float4*)&qN[row * 64 + dg] = qv;
            float4 kv = *(const float4*)(qbase + (size_t)row * 1536 + 512 + h * 64 + dg);
            kT[(dg + 0) * 68 + row] = kv.x;
            kT[(dg + 1) * 68 + row] = kv.y;
            kT[(dg + 2) * 68 + row] = kv.z;
            kT[(dg + 3) * 68 + row] = kv.w;
        }
        __syncthreads();

        // s = q @ k^T (q already scaled)
        float acc[4][4];
#pragma unroll
        for (int i = 0; i < 4; i++)
#pragma unroll
            for (int j = 0; j < 4; j++) acc[i][j] = 0.f;
#pragma unroll 8
        for (int d = 0; d < 64; d++) {
            float a[4];
#pragma unroll
            for (int i = 0; i < 4; i++) a[i] = qN[(ty * 4 + i) * 64 + d];
            float4 b4 = *(const float4*)&kT[d * 68 + tx * 4];
            float bb[4] = {b4.x, b4.y, b4.z, b4.w};
#pragma unroll
            for (int i = 0; i < 4; i++)
#pragma unroll
                for (int j = 0; j < 4; j++)
                    acc[i][j] += a[i] * bb[j];
        }
        // logits = s*mult + bias
#pragma unroll
        for (int i = 0; i < 4; i++) {
            int I = ty * 4 + i;
#pragma unroll
            for (int j = 0; j < 4; j++) {
                int J = tx * 4 + j;
                int dy = (I >> 3) - (J >> 3) + 7;
                int dx = (I & 7) - (J & 7) + 7;
                float bias = sBias[(dy * 15 + dx) * 8 + h];
                sS[I * 64 + J] = acc[i][j] * sMult[I * 64 + J] + bias;
            }
        }
        __syncthreads();

        // load v into kT buffer (natural layout, stride 68)
        for (int idx = tid; idx < 1024; idx += 256) {
            int row = idx >> 4;
            int dg = (idx & 15) << 2;
            float4 vv = *(const float4*)(qbase + (size_t)row * 1536 + 1024 + h * 64 + dg);
            *(float4*)&kT[row * 68 + dg] = vv;
        }
        // softmax over rows of sS (in place)
        for (int r = warp; r < 64; r += 8) {
            float x0 = sS[r * 64 + lane];
            float x1 = sS[r * 64 + lane + 32];
            float m = fmaxf(x0, x1);
#pragma unroll
            for (int o = 16; o; o >>= 1) m = fmaxf(m, __shfl_xor_sync(0xffffffffu, m, o));
            float e0 = expf(x0 - m), e1 = expf(x1 - m);
            float s = e0 + e1;
#pragma unroll
            for (int o = 16; o; o >>= 1) s += __shfl_xor_sync(0xffffffffu, s, o);
            float inv = 1.0f / s;
            sS[r * 64 + lane] = e0 * inv;
            sS[r * 64 + lane + 32] = e1 * inv;
        }
        __syncthreads();

        // o = p @ v
        float oacc[4][4];
#pragma unroll
        for (int i = 0; i < 4; i++)
#pragma unroll
            for (int j = 0; j < 4; j++) oacc[i][j] = 0.f;
#pragma unroll 8
        for (int j = 0; j < 64; j++) {
            float a[4];
#pragma unroll
            for (int i = 0; i < 4; i++) a[i] = sS[(ty * 4 + i) * 64 + j];
            float4 b4 = *(const float4*)&kT[j * 68 + tx * 4];
            float bb[4] = {b4.x, b4.y, b4.z, b4.w};
#pragma unroll
            for (int i = 0; i < 4; i++)
#pragma unroll
                for (int jj = 0; jj < 4; jj++)
                    oacc[i][jj] += a[i] * bb[jj];
        }
        float* ob = obuf + (size_t)(b * 64) * 512 + h * 64;
#pragma unroll
        for (int i = 0; i < 4; i++)
            *(float4*)(ob + (size_t)(ty * 4 + i) * 512 + tx * 4) =
                make_float4(oacc[i][0], oacc[i][1], oacc[i][2], oacc[i][3]);
        __syncthreads();
    }
}

// =====================================================================
extern "C" void kernel_launch(void* const* d_in, const int* in_sizes, int n_in,
                              void* d_out, int out_size)
{
    const float* x      = (const float*)d_in[0];
    const float* dino   = (const float*)d_in[1];
    const float* point  = (const float*)d_in[2];
    /* d_in[3] color_feature: unused by reference */
    const float* sdf    = (const float*)d_in[4];
    const float* normal = (const float*)d_in[5];
    const float* smask  = (const float*)d_in[6];
    const float* cmask  = (const float*)d_in[7];
    const float* wq     = (const float*)d_in[8];
    const float* bq     = (const float*)d_in[9];
    const float* wkv    = (const float*)d_in[10];
    const float* bkv    = (const float*)d_in[11];
    const float* rel    = (const float*)d_in[12];
    const float* wproj  = (const float*)d_in[13];
    const float* bproj  = (const float*)d_in[14];
    float* out = (float*)d_out;

    float *qkv, *mbuf, *obuf;
    cudaGetSymbolAddress((void**)&qkv, g_qkv);
    cudaGetSymbolAddress((void**)&mbuf, g_mult);
    cudaGetSymbolAddress((void**)&obuf, g_o);

    const int smem_mult = SMEM_MULT_FLOATS * 4;
    const int smem_attn = SMEM_ATTN_FLOATS * 4;
    cudaFuncSetAttribute(mult_kernel, cudaFuncAttributeMaxDynamicSharedMemorySize, smem_mult);
    cudaFuncSetAttribute(attn_kernel, cudaFuncAttributeMaxDynamicSharedMemorySize, smem_attn);

    dim3 blk(256);
    // q = SCALE*(x @ wq^T + bq)  -> qkv cols [0,512)
    sgemm_nt<<<dim3(4, MROWS / 128), blk>>>(x, wq, bq, qkv, 512, 1536, SCALE);
    // kv = x @ wkv^T + bkv       -> qkv cols [512,1536)
    sgemm_nt<<<dim3(8, MROWS / 128), blk>>>(x, wkv, bkv, qkv + 512, 512, 1536, 1.0f);
    // correlation maps
    mult_kernel<<<NB, blk, smem_mult>>>(dino, point, sdf, normal, smask, cmask, mbuf);
    // attention
    attn_kernel<<<NB, blk, smem_attn>>>(mbuf, rel, qkv, obuf);
    // out = o @ wproj^T + bproj
    sgemm_nt<<<dim3(4, MROWS / 128), blk>>>(obuf, wproj, bproj, out, 512, 512, 1.0f);
}

// round 3
// speedup vs baseline: 2.1624x; 2.1624x over previous
#include <cuda_runtime.h>
#include <math.h>
#include <stdint.h>

#define NTOK 64
#define DIM 512
#define HEADS 8
#define NB 2048
#define MROWS (NB * NTOK)   // 131072
#define SCALE 0.125f        // 64^-0.5
#define KDIM 512

// ---------------- scratch (device globals; no allocation) ----------------
static __device__ float g_qkv[(size_t)MROWS * 1536];   // [M,1536]: q|k|v
static __device__ float g_mult[(size_t)NB * NTOK * NTOK];
static __device__ float g_o[(size_t)MROWS * DIM];      // attn out (tf32-rounded)
static __device__ float g_xr[(size_t)MROWS * DIM];     // x rounded to tf32
static __device__ float g_wr[(size_t)2048 * 512];      // wq|wkv|wproj rounded

__device__ __forceinline__ float tf32r(float x) {
    asm("cvt.rna.tf32.f32 %0, %0;" : "+f"(x));
    return x;
}

// ===================== tf32 rounding pass =====================
__global__ void round_kernel(const float* __restrict__ in, float* __restrict__ out, int n4)
{
    int i = blockIdx.x * blockDim.x + threadIdx.x;
    int stride = gridDim.x * blockDim.x;
    for (; i < n4; i += stride) {
        float4 v = ((const float4*)in)[i];
        v.x = tf32r(v.x); v.y = tf32r(v.y); v.z = tf32r(v.z); v.w = tf32r(v.w);
        ((float4*)out)[i] = v;
    }
}

// =====================================================================
// tf32 mma.sync GEMM:  C[m,n] = alpha*( sum_k A[m,k]*B[n,k] + bias[n] )
// A: [M,512], B: [N,512] (K-major, tf32-pre-rounded fp32)
// CTA 128x256, 8 warps (2m x 4n) of 64x64; BK=32; 3-stage cp.async ring
// =====================================================================
#define BK 32
#define APAD_STRIDE 36                       // floats per smem row
#define STAGE_FLOATS ((128 + 256) * APAD_STRIDE)   // 13824
#define STAGE_BYTES (STAGE_FLOATS * 4)             // 55296
#define NSTAGE 3
#define SMEM_GEMM_BYTES (NSTAGE * STAGE_BYTES)     // 165888
#define NCHUNK (KDIM / BK)                         // 16

__device__ __forceinline__ uint32_t smem_u32(const void* p) {
    uint32_t a;
    asm("{ .reg .u64 t; cvta.to.shared.u64 t, %1; cvt.u32.u64 %0, t; }" : "=r"(a) : "l"(p));
    return a;
}
#define CP_ASYNC16(dst, src) \
    asm volatile("cp.async.cg.shared.global [%0], [%1], 16;" :: "r"(dst), "l"(src) : "memory")
#define CP_COMMIT() asm volatile("cp.async.commit_group;" ::: "memory")
#define CP_WAIT2()  asm volatile("cp.async.wait_group 2;" ::: "memory")

__device__ __forceinline__ void mma_tf32(float* d, const uint32_t* a, const uint32_t* b) {
    asm volatile(
        "mma.sync.aligned.m16n8k8.row.col.f32.tf32.tf32.f32 "
        "{%0,%1,%2,%3}, {%4,%5,%6,%7}, {%8,%9}, {%0,%1,%2,%3};"
        : "+f"(d[0]), "+f"(d[1]), "+f"(d[2]), "+f"(d[3])
        : "r"(a[0]), "r"(a[1]), "r"(a[2]), "r"(a[3]), "r"(b[0]), "r"(b[1]));
}

__global__ __launch_bounds__(256, 1)
void gemm_tf32(const float* __restrict__ A, const float* __restrict__ B,
               const float* __restrict__ bias, float* __restrict__ C,
               long ldc, float alpha)
{
    extern __shared__ float smf[];
    const int tid = threadIdx.x;
    const int lane = tid & 31;
    const int wid = tid >> 5;
    const int warp_m = wid & 1;       // 0..1  (64-row slab)
    const int warp_n = wid >> 1;      // 0..3  (64-col slab)
    const long m0 = (long)blockIdx.y * 128;
    const long n0 = (long)blockIdx.x * 256;

    const float* Ag = A + m0 * KDIM;
    const float* Bg = B + n0 * KDIM;
    const uint32_t sb = smem_u32(smf);

    // ---- async chunk copier: A 128x32, B 256x32 -> stage s ----
    auto copy_chunk = [&](int chunk, int s) {
        const int k0 = chunk * BK;
        const uint32_t dstA = sb + s * STAGE_BYTES;
        const uint32_t dstB = dstA + 128 * APAD_STRIDE * 4;
#pragma unroll
        for (int i = 0; i < 4; i++) {
            int idx = tid + i * 256;          // 0..1023
            int row = idx >> 3, q = idx & 7;
            CP_ASYNC16(dstA + row * (APAD_STRIDE * 4) + q * 16,
                       Ag + (long)row * KDIM + k0 + q * 4);
        }
#pragma unroll
        for (int i = 0; i < 8; i++) {
            int idx = tid + i * 256;          // 0..2047
            int row = idx >> 3, q = idx & 7;
            CP_ASYNC16(dstB + row * (APAD_STRIDE * 4) + q * 16,
                       Bg + (long)row * KDIM + k0 + q * 4);
        }
        CP_COMMIT();
    };

    float acc[4][8][4];
#pragma unroll
    for (int mt = 0; mt < 4; mt++)
#pragma unroll
        for (int nt = 0; nt < 8; nt++)
#pragma unroll
            for (int e = 0; e < 4; e++) acc[mt][nt][e] = 0.f;

    copy_chunk(0, 0);
    copy_chunk(1, 1);
    copy_chunk(2, 2);

    const int r = lane >> 2;          // 0..7
    const int cc = lane & 3;          // 0..3

    for (int c = 0; c < NCHUNK; c++) {
        const int s = c % NSTAGE;
        CP_WAIT2();
        __syncthreads();

        const float* sA = smf + s * STAGE_FLOATS;
        const float* sB = sA + 128 * APAD_STRIDE;
        const float* aB = sA + (warp_m * 64 + r) * APAD_STRIDE + cc;
        const float* bB = sB + (warp_n * 64 + r) * APAD_STRIDE + cc;

#pragma unroll
        for (int k8 = 0; k8 < 4; k8++) {
            uint32_t af[4][4];
#pragma unroll
            for (int mt = 0; mt < 4; mt++) {
                const float* ap = aB + mt * 16 * APAD_STRIDE + k8 * 8;
                af[mt][0] = __float_as_uint(ap[0]);
                af[mt][1] = __float_as_uint(ap[8 * APAD_STRIDE]);
                af[mt][2] = __float_as_uint(ap[4]);
                af[mt][3] = __float_as_uint(ap[8 * APAD_STRIDE + 4]);
            }
            uint32_t bf[8][2];
#pragma unroll
            for (int nt = 0; nt < 8; nt++) {
                const float* bp = bB + nt * 8 * APAD_STRIDE + k8 * 8;
                bf[nt][0] = __float_as_uint(bp[0]);
                bf[nt][1] = __float_as_uint(bp[4]);
            }
#pragma unroll
            for (int mt = 0; mt < 4; mt++)
#pragma unroll
                for (int nt = 0; nt < 8; nt++)
                    mma_tf32(acc[mt][nt], af[mt], bf[nt]);
        }
        __syncthreads();
        if (c + 3 < NCHUNK) copy_chunk(c + 3, s);
        else CP_COMMIT();   // keep wait_group accounting in the tail
    }

    // ---- epilogue: acc -> smem (stride 264) -> coalesced gmem ----
    {
        float* se = smf;
        const int row0 = warp_m * 64;
        const int col0 = warp_n * 64;
#pragma unroll
        for (int mt = 0; mt < 4; mt++)
#pragma unroll
            for (int nt = 0; nt < 8; nt++) {
                int rr = row0 + mt * 16 + r;
                int cb = col0 + nt * 8 + 2 * cc;
                *(float2*)(se + rr * 264 + cb) =
                    make_float2(acc[mt][nt][0], acc[mt][nt][1]);
                *(float2*)(se + (rr + 8) * 264 + cb) =
                    make_float2(acc[mt][nt][2], acc[mt][nt][3]);
            }
    }
    __syncthreads();
#pragma unroll
    for (int i = 0; i < 32; i++) {
        int idx = tid + i * 256;          // 0..8191
        int row = idx >> 6;
        int c4 = (idx & 63) * 4;
        float4 v = *(const float4*)(smf + row * 264 + c4);
        float4 bv = *(const float4*)(bias + n0 + c4);
        float4 o;
        o.x = alpha * (v.x + bv.x);
        o.y = alpha * (v.y + bv.y);
        o.z = alpha * (v.z + bv.z);
        o.w = alpha * (v.w + bv.w);
        *(float4*)(C + (m0 + row) * ldc + n0 + c4) = o;
    }
}

// =====================================================================
// Correlation-map kernel: one block per window, mult[b][i][j]
// =====================================================================
#define SMEM_MULT_FLOATS (384*64 + 16*64 + 64 + 64 + 192 + 192 + 64 + 512)

__global__ __launch_bounds__(256)
void mult_kernel(const float* __restrict__ dino, const float* __restrict__ point,
                 const float* __restrict__ sdf, const float* __restrict__ normal,
                 const float* __restrict__ smask, const float* __restrict__ cmask,
                 float* __restrict__ mout)
{
    extern __shared__ float sm[];
    float* sDT   = sm;               // [384][64] dino transposed
    float* sST   = sDT + 384 * 64;   // [16][64]  sdf transposed
    float* rnD   = sST + 16 * 64;    // [64]
    float* rnS   = rnD + 64;         // [64]
    float* sp    = rnS + 64;         // [64][3]
    float* sn    = sp + 192;         // [64][3]
    float* scode = sn + 192;         // [64]
    float* scl   = scode + 64;       // [64][8]

    const int b = blockIdx.x;
    const int tid = threadIdx.x;

    const float* dg = dino + (size_t)b * 64 * 384;
    for (int idx = tid; idx < 64 * 96; idx += 256) {
        int row = idx / 96;
        int kg = (idx % 96) * 4;
        float4 v = *(const float4*)(dg + row * 384 + kg);
        sDT[(kg + 0) * 64 + row] = v.x;
        sDT[(kg + 1) * 64 + row] = v.y;
        sDT[(kg + 2) * 64 + row] = v.z;
        sDT[(kg + 3) * 64 + row] = v.w;
    }
    const float* sg = sdf + (size_t)b * 64 * 16;
    {
        int idx = tid;
        int row = idx >> 2;
        int kg = (idx & 3) * 4;
        float4 v = *(const float4*)(sg + row * 16 + kg);
        sST[(kg + 0) * 64 + row] = v.x;
        sST[(kg + 1) * 64 + row] = v.y;
        sST[(kg + 2) * 64 + row] = v.z;
        sST[(kg + 3) * 64 + row] = v.w;
    }
    if (tid < 192) {
        sp[tid] = point[(size_t)b * 192 + tid];
        sn[tid] = normal[(size_t)b * 192 + tid];
    }
    if (tid < 64)
        scode[tid] = (smask[(size_t)b * 64 + tid] < 0.1f) ? 1.f : 2.f;
    for (int idx = tid; idx < 512; idx += 256)
        scl[idx] = cmask[(size_t)b * 512 + idx];
    __syncthreads();

    if (tid < 64) {
        float s = 0.f;
        for (int k = 0; k < 384; k++) { float v = sDT[k * 64 + tid]; s += v * v; }
        float nn = fminf(fmaxf(sqrtf(s), 1e-20f), 1e10f);
        rnD[tid] = 1.0f / nn;
        float s2 = 0.f;
        for (int k = 0; k < 16; k++) { float v = sST[k * 64 + tid]; s2 += v * v; }
        nn = fminf(fmaxf(sqrtf(s2), 1e-20f), 1e10f);
        rnS[tid] = 1.0f / nn;
    }
    __syncthreads();

    const int tx = tid & 15, ty = tid >> 4;
    float dacc[4][4], sacc[4][4];
#pragma unroll
    for (int i = 0; i < 4; i++)
#pragma unroll
        for (int j = 0; j < 4; j++) { dacc[i][j] = 0.f; sacc[i][j] = 0.f; }

#pragma unroll 4
    for (int k = 0; k < 384; k++) {
        float4 a4 = *(const float4*)&sDT[k * 64 + ty * 4];
        float4 b4 = *(const float4*)&sDT[k * 64 + tx * 4];
        float a[4] = {a4.x, a4.y, a4.z, a4.w};
        float b[4] = {b4.x, b4.y, b4.z, b4.w};
#pragma unroll
        for (int i = 0; i < 4; i++)
#pragma unroll
            for (int j = 0; j < 4; j++)
                dacc[i][j] += a[i] * b[j];
    }
#pragma unroll
    for (int k = 0; k < 16; k++) {
        float4 a4 = *(const float4*)&sST[k * 64 + ty * 4];
        float4 b4 = *(const float4*)&sST[k * 64 + tx * 4];
        float a[4] = {a4.x, a4.y, a4.z, a4.w};
        float b[4] = {b4.x, b4.y, b4.z, b4.w};
#pragma unroll
        for (int i = 0; i < 4; i++)
#pragma unroll
            for (int j = 0; j < 4; j++)
                sacc[i][j] += a[i] * b[j];
    }

    float* mrow = mout + (size_t)b * 4096;
#pragma unroll
    for (int i = 0; i < 4; i++) {
        int I = ty * 4 + i;
        float res[4];
#pragma unroll
        for (int j = 0; j < 4; j++) {
            int J = tx * 4 + j;
            float dmap = fminf(fmaxf(dacc[i][j] * rnD[I] * rnD[J], 0.f), 1e10f);
            float smap = 1.f - fminf(fmaxf(sacc[i][j] * rnS[I] * rnS[J], 0.f), 1.f);
            float P1 = 0.f, P2 = 0.f;
#pragma unroll
            for (int d = 0; d < 3; d++) {
                float diff = sp[I * 3 + d] - sp[J * 3 + d];
                P1 += diff * sn[I * 3 + d];
                P2 += diff * sn[J * 3 + d];
            }
            float plane = expf(-0.5f * (fabsf(P1) + fabsf(P2)));
            float mm = (scode[I] * scode[J] == 2.f) ? 1.f : 0.2f;
            float cc = 0.f;
#pragma unroll
            for (int c = 0; c < 8; c++) cc += scl[I * 8 + c] * scl[J * 8 + c];
            res[j] = dmap * smap * plane * cc * mm;
        }
        *(float4*)(mrow + I * 64 + tx * 4) = make_float4(res[0], res[1], res[2], res[3]);
    }
}

// =====================================================================
// Attention kernel: one block per window, loops over 8 heads
// (output rounded to tf32 for the proj GEMM)
// =====================================================================
#define SMEM_ATTN_FLOATS (64*64 + 64*68 + 64*64 + 64*64 + 225*8)

__global__ __launch_bounds__(256)
void attn_kernel(const float* __restrict__ mult, const float* __restrict__ rel_table,
                 const float* __restrict__ qkv, float* __restrict__ obuf)
{
    extern __shared__ float sm[];
    float* qN    = sm;               // [64][64]
    float* kT    = qN + 64 * 64;     // [64][68]
    float* sS    = kT + 64 * 68;     // [64][64]
    float* sMult = sS + 64 * 64;     // [64][64]
    float* sBias = sMult + 64 * 64;  // [225*8]

    const int b = blockIdx.x;
    const int tid = threadIdx.x;
    const int tx = tid & 15, ty = tid >> 4;
    const int lane = tid & 31, warp = tid >> 5;

    for (int i = tid; i < 1024; i += 256)
        ((float4*)sMult)[i] = ((const float4*)(mult + (size_t)b * 4096))[i];
    for (int i = tid; i < 1800; i += 256)
        sBias[i] = rel_table[i];

    const float* qbase = qkv + (size_t)(b * 64) * 1536;

    for (int h = 0; h < HEADS; h++) {
        for (int idx = tid; idx < 1024; idx += 256) {
            int row = idx >> 4;
            int dg = (idx & 15) << 2;
            float4 qv = *(const float4*)(qbase + (size_t)row * 1536 + h * 64 + dg);
            *(float4*)&qN[row * 64 + dg] = qv;
            float4 kv = *(const float4*)(qbase + (size_t)row * 1536 + 512 + h * 64 + dg);
            kT[(dg + 0) * 68 + row] = kv.x;
            kT[(dg + 1) * 68 + row] = kv.y;
            kT[(dg + 2) * 68 + row] = kv.z;
            kT[(dg + 3) * 68 + row] = kv.w;
        }
        __syncthreads();

        float acc[4][4];
#pragma unroll
        for (int i = 0; i < 4; i++)
#pragma unroll
            for (int j = 0; j < 4; j++) acc[i][j] = 0.f;
#pragma unroll 8
        for (int d = 0; d < 64; d++) {
            float a[4];
#pragma unroll
            for (int i = 0; i < 4; i++) a[i] = qN[(ty * 4 + i) * 64 + d];
            float4 b4 = *(const float4*)&kT[d * 68 + tx * 4];
            float bb[4] = {b4.x, b4.y, b4.z, b4.w};
#pragma unroll
            for (int i = 0; i < 4; i++)
#pragma unroll
                for (int j = 0; j < 4; j++)
                    acc[i][j] += a[i] * bb[j];
        }
#pragma unroll
        for (int i = 0; i < 4; i++) {
            int I = ty * 4 + i;
#pragma unroll
            for (int j = 0; j < 4; j++) {
                int J = tx * 4 + j;
                int dy = (I >> 3) - (J >> 3) + 7;
                int dx = (I & 7) - (J & 7) + 7;
                float bias = sBias[(dy * 15 + dx) * 8 + h];
                sS[I * 64 + J] = acc[i][j] * sMult[I * 64 + J] + bias;
            }
        }
        __syncthreads();

        for (int idx = tid; idx < 1024; idx += 256) {
            int row = idx >> 4;
            int dg = (idx & 15) << 2;
            float4 vv = *(const float4*)(qbase + (size_t)row * 1536 + 1024 + h * 64 + dg);
            *(float4*)&kT[row * 68 + dg] = vv;
        }
        for (int r = warp; r < 64; r += 8) {
            float x0 = sS[r * 64 + lane];
            float x1 = sS[r * 64 + lane + 32];
            float m = fmaxf(x0, x1);
#pragma unroll
            for (int o = 16; o; o >>= 1) m = fmaxf(m, __shfl_xor_sync(0xffffffffu, m, o));
            float e0 = expf(x0 - m), e1 = expf(x1 - m);
            float s = e0 + e1;
#pragma unroll
            for (int o = 16; o; o >>= 1) s += __shfl_xor_sync(0xffffffffu, s, o);
            float inv = 1.0f / s;
            sS[r * 64 + lane] = e0 * inv;
            sS[r * 64 + lane + 32] = e1 * inv;
        }
        __syncthreads();

        float oacc[4][4];
#pragma unroll
        for (int i = 0; i < 4; i++)
#pragma unroll
            for (int j = 0; j < 4; j++) oacc[i][j] = 0.f;
#pragma unroll 8
        for (int j = 0; j < 64; j++) {
            float a[4];
#pragma unroll
            for (int i = 0; i < 4; i++) a[i] = sS[(ty * 4 + i) * 64 + j];
            float4 b4 = *(const float4*)&kT[j * 68 + tx * 4];
            float bb[4] = {b4.x, b4.y, b4.z, b4.w};
#pragma unroll
            for (int i = 0; i < 4; i++)
#pragma unroll
                for (int jj = 0; jj < 4; jj++)
                    oacc[i][jj] += a[i] * bb[jj];
        }
        float* ob = obuf + (size_t)(b * 64) * 512 + h * 64;
#pragma unroll
        for (int i = 0; i < 4; i++) {
            float4 o4 = make_float4(tf32r(oacc[i][0]), tf32r(oacc[i][1]),
                                    tf32r(oacc[i][2]), tf32r(oacc[i][3]));
            *(float4*)(ob + (size_t)(ty * 4 + i) * 512 + tx * 4) = o4;
        }
        __syncthreads();
    }
}

// =====================================================================
extern "C" void kernel_launch(void* const* d_in, const int* in_sizes, int n_in,
                              void* d_out, int out_size)
{
    const float* x      = (const float*)d_in[0];
    const float* dino   = (const float*)d_in[1];
    const float* point  = (const float*)d_in[2];
    /* d_in[3] color_feature: unused by reference */
    const float* sdf    = (const float*)d_in[4];
    const float* normal = (const float*)d_in[5];
    const float* smask  = (const float*)d_in[6];
    const float* cmask  = (const float*)d_in[7];
    const float* wq     = (const float*)d_in[8];
    const float* bq     = (const float*)d_in[9];
    const float* wkv    = (const float*)d_in[10];
    const float* bkv    = (const float*)d_in[11];
    const float* rel    = (const float*)d_in[12];
    const float* wproj  = (const float*)d_in[13];
    const float* bproj  = (const float*)d_in[14];
    float* out = (float*)d_out;

    float *qkv, *mbuf, *obuf, *xr, *wr;
    cudaGetSymbolAddress((void**)&qkv, g_qkv);
    cudaGetSymbolAddress((void**)&mbuf, g_mult);
    cudaGetSymbolAddress((void**)&obuf, g_o);
    cudaGetSymbolAddress((void**)&xr, g_xr);
    cudaGetSymbolAddress((void**)&wr, g_wr);

    const int smem_mult = SMEM_MULT_FLOATS * 4;
    const int smem_attn = SMEM_ATTN_FLOATS * 4;
    cudaFuncSetAttribute(mult_kernel, cudaFuncAttributeMaxDynamicSharedMemorySize, smem_mult);
    cudaFuncSetAttribute(attn_kernel, cudaFuncAttributeMaxDynamicSharedMemorySize, smem_attn);
    cudaFuncSetAttribute(gemm_tf32, cudaFuncAttributeMaxDynamicSharedMemorySize, SMEM_GEMM_BYTES);

    dim3 blk(256);

    // tf32 pre-round: x and weights
    round_kernel<<<1184, 256>>>(x, xr, (MROWS * DIM) / 4);
    round_kernel<<<128, 256>>>(wq, wr, (512 * 512) / 4);
    round_kernel<<<128, 256>>>(wkv, wr + 512 * 512, (1024 * 512) / 4);
    round_kernel<<<128, 256>>>(wproj, wr + 1536 * 512, (512 * 512) / 4);

    // q = SCALE*(x @ wq^T + bq)  -> qkv cols [0,512)
    gemm_tf32<<<dim3(2, MROWS / 128), blk, SMEM_GEMM_BYTES>>>(
        xr, wr, bq, qkv, 1536, SCALE);
    // kv = x @ wkv^T + bkv       -> qkv cols [512,1536)
    gemm_tf32<<<dim3(4, MROWS / 128), blk, SMEM_GEMM_BYTES>>>(
        xr, wr + 512 * 512, bkv, qkv + 512, 1536, 1.0f);
    // correlation maps
    mult_kernel<<<NB, blk, smem_mult>>>(dino, point, sdf, normal, smask, cmask, mbuf);
    // attention (writes tf32-rounded o)
    attn_kernel<<<NB, blk, smem_attn>>>(mbuf, rel, qkv, obuf);
    // out = o @ wproj^T + bproj
    gemm_tf32<<<dim3(2, MROWS / 128), blk, SMEM_GEMM_BYTES>>>(
        obuf, wr + 1536 * 512, bproj, out, 512, 1.0f);
}

// round 4
// speedup vs baseline: 2.5759x; 1.1912x over previous
#include <cuda_runtime.h>
#include <math.h>
#include <stdint.h>

#define NTOK 64
#define DIM 512
#define HEADS 8
#define NB 2048
#define MROWS (NB * NTOK)   // 131072
#define SCALE 0.125f        // 64^-0.5
#define KDIM 512

// ---------------- scratch (device globals; no allocation) ----------------
static __device__ float g_qkv[(size_t)MROWS * 1536];   // [M,1536]: q(scaled)|k|v
static __device__ float g_mult[(size_t)NB * NTOK * NTOK];
static __device__ float g_o[(size_t)MROWS * DIM];      // attn out (tf32-rounded)
static __device__ float g_xr[(size_t)MROWS * DIM];     // x rounded to tf32
static __device__ float g_wr[(size_t)2048 * 512];      // wq(scaled)|wkv|wproj rounded
static __device__ float g_bias[1536];                  // SCALE*bq | bkv

__device__ __forceinline__ float tf32r(float x) {
    asm("cvt.rna.tf32.f32 %0, %0;" : "+f"(x));
    return x;
}
__device__ __forceinline__ uint32_t smem_u32(const void* p) {
    uint32_t a;
    asm("{ .reg .u64 t; cvta.to.shared.u64 t, %1; cvt.u32.u64 %0, t; }" : "=r"(a) : "l"(p));
    return a;
}
#define CP_ASYNC16(dst, src) \
    asm volatile("cp.async.cg.shared.global [%0], [%1], 16;" :: "r"(dst), "l"(src) : "memory")
#define CP_COMMIT() asm volatile("cp.async.commit_group;" ::: "memory")
#define CP_WAIT2()  asm volatile("cp.async.wait_group 2;" ::: "memory")

__device__ __forceinline__ void mma_tf32(float* d, const uint32_t* a, const uint32_t* b) {
    asm volatile(
        "mma.sync.aligned.m16n8k8.row.col.f32.tf32.tf32.f32 "
        "{%0,%1,%2,%3}, {%4,%5,%6,%7}, {%8,%9}, {%0,%1,%2,%3};"
        : "+f"(d[0]), "+f"(d[1]), "+f"(d[2]), "+f"(d[3])
        : "r"(a[0]), "r"(a[1]), "r"(a[2]), "r"(a[3]), "r"(b[0]), "r"(b[1]));
}

// ===================== tf32 rounding pass (optional scale) =====================
__global__ void round_kernel(const float* __restrict__ in, float* __restrict__ out,
                             int n4, float s)
{
    int i = blockIdx.x * blockDim.x + threadIdx.x;
    int stride = gridDim.x * blockDim.x;
    for (; i < n4; i += stride) {
        float4 v = ((const float4*)in)[i];
        v.x = tf32r(v.x * s); v.y = tf32r(v.y * s);
        v.z = tf32r(v.z * s); v.w = tf32r(v.w * s);
        ((float4*)out)[i] = v;
    }
}

__global__ void bias_combine(const float* __restrict__ bq, const float* __restrict__ bkv,
                             float* __restrict__ gb)
{
    int i = blockIdx.x * blockDim.x + threadIdx.x;
    if (i < 1536) gb[i] = (i < 512) ? bq[i] * SCALE : bkv[i - 512];
}

// =====================================================================
// tf32 mma.sync GEMM:  C[m,n] = alpha*( sum_k A[m,k]*B[n,k] + bias[n] )
// CTA 128x256, 8 warps (2m x 4n) of 64x64; BK=32; 3-stage cp.async ring
// =====================================================================
#define BK 32
#define APAD_STRIDE 36
#define STAGE_FLOATS ((128 + 256) * APAD_STRIDE)
#define STAGE_BYTES (STAGE_FLOATS * 4)
#define NSTAGE 3
#define SMEM_GEMM_BYTES (NSTAGE * STAGE_BYTES)
#define NCHUNK (KDIM / BK)

__global__ __launch_bounds__(256, 1)
void gemm_tf32(const float* __restrict__ A, const float* __restrict__ B,
               const float* __restrict__ bias, float* __restrict__ C,
               long ldc, float alpha)
{
    extern __shared__ float smf[];
    const int tid = threadIdx.x;
    const int lane = tid & 31;
    const int wid = tid >> 5;
    const int warp_m = wid & 1;
    const int warp_n = wid >> 1;
    const long m0 = (long)blockIdx.y * 128;
    const long n0 = (long)blockIdx.x * 256;

    const float* Ag = A + m0 * KDIM;
    const float* Bg = B + n0 * KDIM;
    const uint32_t sb = smem_u32(smf);

    auto copy_chunk = [&](int chunk, int s) {
        const int k0 = chunk * BK;
        const uint32_t dstA = sb + s * STAGE_BYTES;
        const uint32_t dstB = dstA + 128 * APAD_STRIDE * 4;
#pragma unroll
        for (int i = 0; i < 4; i++) {
            int idx = tid + i * 256;
            int row = idx >> 3, q = idx & 7;
            CP_ASYNC16(dstA + row * (APAD_STRIDE * 4) + q * 16,
                       Ag + (long)row * KDIM + k0 + q * 4);
        }
#pragma unroll
        for (int i = 0; i < 8; i++) {
            int idx = tid + i * 256;
            int row = idx >> 3, q = idx & 7;
            CP_ASYNC16(dstB + row * (APAD_STRIDE * 4) + q * 16,
                       Bg + (long)row * KDIM + k0 + q * 4);
        }
        CP_COMMIT();
    };

    float acc[4][8][4];
#pragma unroll
    for (int mt = 0; mt < 4; mt++)
#pragma unroll
        for (int nt = 0; nt < 8; nt++)
#pragma unroll
            for (int e = 0; e < 4; e++) acc[mt][nt][e] = 0.f;

    copy_chunk(0, 0);
    copy_chunk(1, 1);
    copy_chunk(2, 2);

    const int r = lane >> 2;
    const int cc = lane & 3;

    for (int c = 0; c < NCHUNK; c++) {
        const int s = c % NSTAGE;
        CP_WAIT2();
        __syncthreads();

        const float* sA = smf + s * STAGE_FLOATS;
        const float* sB = sA + 128 * APAD_STRIDE;
        const float* aB = sA + (warp_m * 64 + r) * APAD_STRIDE + cc;
        const float* bB = sB + (warp_n * 64 + r) * APAD_STRIDE + cc;

#pragma unroll
        for (int k8 = 0; k8 < 4; k8++) {
            uint32_t af[4][4];
#pragma unroll
            for (int mt = 0; mt < 4; mt++) {
                const float* ap = aB + mt * 16 * APAD_STRIDE + k8 * 8;
                af[mt][0] = __float_as_uint(ap[0]);
                af[mt][1] = __float_as_uint(ap[8 * APAD_STRIDE]);
                af[mt][2] = __float_as_uint(ap[4]);
                af[mt][3] = __float_as_uint(ap[8 * APAD_STRIDE + 4]);
            }
            uint32_t bf[8][2];
#pragma unroll
            for (int nt = 0; nt < 8; nt++) {
                const float* bp = bB + nt * 8 * APAD_STRIDE + k8 * 8;
                bf[nt][0] = __float_as_uint(bp[0]);
                bf[nt][1] = __float_as_uint(bp[4]);
            }
#pragma unroll
            for (int mt = 0; mt < 4; mt++)
#pragma unroll
                for (int nt = 0; nt < 8; nt++)
                    mma_tf32(acc[mt][nt], af[mt], bf[nt]);
        }
        __syncthreads();
        if (c + 3 < NCHUNK) copy_chunk(c + 3, s);
        else CP_COMMIT();
    }

    // epilogue via smem for coalesced stores
    {
        float* se = smf;
        const int row0 = warp_m * 64;
        const int col0 = warp_n * 64;
#pragma unroll
        for (int mt = 0; mt < 4; mt++)
#pragma unroll
            for (int nt = 0; nt < 8; nt++) {
                int rr = row0 + mt * 16 + r;
                int cb = col0 + nt * 8 + 2 * cc;
                *(float2*)(se + rr * 264 + cb) =
                    make_float2(acc[mt][nt][0], acc[mt][nt][1]);
                *(float2*)(se + (rr + 8) * 264 + cb) =
                    make_float2(acc[mt][nt][2], acc[mt][nt][3]);
            }
    }
    __syncthreads();
#pragma unroll
    for (int i = 0; i < 32; i++) {
        int idx = tid + i * 256;
        int row = idx >> 6;
        int c4 = (idx & 63) * 4;
        float4 v = *(const float4*)(smf + row * 264 + c4);
        float4 bv = *(const float4*)(bias + n0 + c4);
        float4 o;
        o.x = alpha * (v.x + bv.x);
        o.y = alpha * (v.y + bv.y);
        o.z = alpha * (v.z + bv.z);
        o.w = alpha * (v.w + bv.w);
        *(float4*)(C + (m0 + row) * ldc + n0 + c4) = o;
    }
}

// =====================================================================
// Correlation-map kernel: tf32 mma for the 384-K dino Gram matrix
// =====================================================================
#define DSTRIDE 100     // 96 + 4 pad (100 mod 32 == 4 -> conflict-free frags)
#define SMEM_MULT_FLOATS (2*64*DSTRIDE + 64*68 + 64*17 + 64 + 64 + 192 + 192 + 64 + 512)

__global__ __launch_bounds__(256)
void mult_kernel(const float* __restrict__ dino, const float* __restrict__ point,
                 const float* __restrict__ sdf, const float* __restrict__ normal,
                 const float* __restrict__ smask, const float* __restrict__ cmask,
                 float* __restrict__ mout)
{
    extern __shared__ float sm[];
    float* sD    = sm;                    // 2 x [64][100] dino chunk (tf32)
    float* sG    = sD + 2 * 64 * DSTRIDE; // [64][68] Gram
    float* sSF   = sG + 64 * 68;          // [64][17] sdf natural (exact)
    float* rnD   = sSF + 64 * 17;
    float* rnS   = rnD + 64;
    float* sp    = rnS + 64;              // [64][3]
    float* sn    = sp + 192;              // [64][3]
    float* scode = sn + 192;              // [64]
    float* scl   = scode + 64;            // [64][8]

    const int b = blockIdx.x;
    const int tid = threadIdx.x;
    const int lane = tid & 31, w = tid >> 5;
    const int r = lane >> 2, cc = lane & 3;
    const int m0 = (w & 3) * 16, n0 = (w >> 2) * 32;

    // ---- misc loads ----
    const float* sg = sdf + (size_t)b * 64 * 16;
    {   // 256 threads: each one float4 of sdf -> natural stride 17
        int row = tid >> 2;
        int kg = (tid & 3) * 4;
        float4 v = *(const float4*)(sg + row * 16 + kg);
        sSF[row * 17 + kg + 0] = v.x;
        sSF[row * 17 + kg + 1] = v.y;
        sSF[row * 17 + kg + 2] = v.z;
        sSF[row * 17 + kg + 3] = v.w;
    }
    if (tid < 192) {
        sp[tid] = point[(size_t)b * 192 + tid];
        sn[tid] = normal[(size_t)b * 192 + tid];
    }
    if (tid < 64)
        scode[tid] = (smask[(size_t)b * 64 + tid] < 0.1f) ? 1.f : 2.f;
    for (int idx = tid; idx < 512; idx += 256)
        scl[idx] = cmask[(size_t)b * 512 + idx];

    // ---- dino Gram via tf32 mma, 4 chunks of K=96, double-buffered ----
    const float* dg = dino + (size_t)b * 64 * 384;
    auto load_chunk = [&](int kc, int buf) {
        float* dst = sD + buf * 64 * DSTRIDE;
        const int k0 = kc * 96;
#pragma unroll
        for (int i = 0; i < 6; i++) {
            int idx = tid + i * 256;          // 0..1535
            int row = idx / 24;
            int q = idx % 24;
            float4 v = *(const float4*)(dg + row * 384 + k0 + q * 4);
            v.x = tf32r(v.x); v.y = tf32r(v.y); v.z = tf32r(v.z); v.w = tf32r(v.w);
            *(float4*)(dst + row * DSTRIDE + q * 4) = v;
        }
    };

    float gacc[4][4];
#pragma unroll
    for (int i = 0; i < 4; i++)
#pragma unroll
        for (int j = 0; j < 4; j++) gacc[i][j] = 0.f;

    load_chunk(0, 0);
    __syncthreads();
    for (int c = 0; c < 4; c++) {
        if (c + 1 < 4) load_chunk(c + 1, (c + 1) & 1);
        const float* buf = sD + (c & 1) * 64 * DSTRIDE;
        const float* aB = buf + (m0 + r) * DSTRIDE + cc;
#pragma unroll
        for (int k8 = 0; k8 < 12; k8++) {
            uint32_t af[4];
            const float* ap = aB + k8 * 8;
            af[0] = __float_as_uint(ap[0]);
            af[1] = __float_as_uint(ap[8 * DSTRIDE]);
            af[2] = __float_as_uint(ap[4]);
            af[3] = __float_as_uint(ap[8 * DSTRIDE + 4]);
#pragma unroll
            for (int nt = 0; nt < 4; nt++) {
                const float* bp = buf + (n0 + nt * 8 + r) * DSTRIDE + cc + k8 * 8;
                uint32_t bf[2] = { __float_as_uint(bp[0]), __float_as_uint(bp[4]) };
                mma_tf32(gacc[nt], af, bf);
            }
        }
        __syncthreads();
    }
    // write Gram fragments to sG
#pragma unroll
    for (int nt = 0; nt < 4; nt++) {
        int col = n0 + nt * 8 + 2 * cc;
        int I0 = m0 + r, I1 = I0 + 8;
        sG[I0 * 68 + col]     = gacc[nt][0];
        sG[I0 * 68 + col + 1] = gacc[nt][1];
        sG[I1 * 68 + col]     = gacc[nt][2];
        sG[I1 * 68 + col + 1] = gacc[nt][3];
    }
    __syncthreads();

    // norms: dino from Gram diagonal; sdf exact
    if (tid < 64) {
        float nn = fminf(fmaxf(sqrtf(fmaxf(sG[tid * 68 + tid], 0.f)), 1e-20f), 1e10f);
        rnD[tid] = 1.0f / nn;
        float s2 = 0.f;
#pragma unroll
        for (int k = 0; k < 16; k++) { float v = sSF[tid * 17 + k]; s2 += v * v; }
        nn = fminf(fmaxf(sqrtf(s2), 1e-20f), 1e10f);
        rnS[tid] = 1.0f / nn;
    }
    __syncthreads();

    // epilogue: 4x4 per thread
    const int tx = tid & 15, ty = tid >> 4;
    float sacc[4][4];
#pragma unroll
    for (int i = 0; i < 4; i++)
#pragma unroll
        for (int j = 0; j < 4; j++) sacc[i][j] = 0.f;
#pragma unroll
    for (int c = 0; c < 16; c++) {
        float aS[4], bS[4];
#pragma unroll
        for (int i = 0; i < 4; i++) aS[i] = sSF[(ty * 4 + i) * 17 + c];
#pragma unroll
        for (int j = 0; j < 4; j++) bS[j] = sSF[(tx * 4 + j) * 17 + c];
#pragma unroll
        for (int i = 0; i < 4; i++)
#pragma unroll
            for (int j = 0; j < 4; j++)
                sacc[i][j] += aS[i] * bS[j];
    }

    float* mrow = mout + (size_t)b * 4096;
#pragma unroll
    for (int i = 0; i < 4; i++) {
        int I = ty * 4 + i;
        float res[4];
#pragma unroll
        for (int j = 0; j < 4; j++) {
            int J = tx * 4 + j;
            float dmap = fminf(fmaxf(sG[I * 68 + J] * rnD[I] * rnD[J], 0.f), 1e10f);
            float smap = 1.f - fminf(fmaxf(sacc[i][j] * rnS[I] * rnS[J], 0.f), 1.f);
            float P1 = 0.f, P2 = 0.f;
#pragma unroll
            for (int d = 0; d < 3; d++) {
                float diff = sp[I * 3 + d] - sp[J * 3 + d];
                P1 += diff * sn[I * 3 + d];
                P2 += diff * sn[J * 3 + d];
            }
            float plane = expf(-0.5f * (fabsf(P1) + fabsf(P2)));
            float mm = (scode[I] * scode[J] == 2.f) ? 1.f : 0.2f;
            float ccv = 0.f;
#pragma unroll
            for (int c = 0; c < 8; c++) ccv += scl[I * 8 + c] * scl[J * 8 + c];
            res[j] = dmap * smap * plane * ccv * mm;
        }
        *(float4*)(mrow + I * 64 + tx * 4) = make_float4(res[0], res[1], res[2], res[3]);
    }
}

// =====================================================================
// Attention kernel: tf32 mma for QK^T and P@V; smem softmax
// =====================================================================
#define SMEM_ATTN_FLOATS (4*64*68 + 64*68 + 225*8)

__device__ __forceinline__ float relbias(const float* sBias, int I, int J, int h) {
    int dy = (I >> 3) - (J >> 3) + 7;
    int dx = (I & 7) - (J & 7) + 7;
    return sBias[(dy * 15 + dx) * 8 + h];
}

__global__ __launch_bounds__(256)
void attn_kernel(const float* __restrict__ mult, const float* __restrict__ rel_table,
                 const float* __restrict__ qkv, float* __restrict__ obuf)
{
    extern __shared__ float sm[];
    float* qN    = sm;               // [64][68]  q natural (tf32)
    float* kN    = qN + 64 * 68;     // [64][68]  k natural (tf32)
    float* vT    = kN + 64 * 68;     // [64][68]  v transposed (tf32)
    float* sS    = vT + 64 * 68;     // [64][68]  v-staging / logits / probs
    float* sMult = sS + 64 * 68;     // [64][68]
    float* sBias = sMult + 64 * 68;  // [225*8]

    const int b = blockIdx.x;
    const int tid = threadIdx.x;
    const int lane = tid & 31, w = tid >> 5;
    const int r = lane >> 2, cc = lane & 3;
    const int m0 = (w & 3) * 16, n0 = (w >> 2) * 32;

    for (int idx = tid; idx < 1024; idx += 256) {
        int row = idx >> 4;
        int c4 = (idx & 15) * 4;
        float4 v = *(const float4*)(mult + (size_t)b * 4096 + row * 64 + c4);
        *(float4*)(sMult + row * 68 + c4) = v;
    }
    for (int i = tid; i < 1800; i += 256)
        sBias[i] = rel_table[i];

    const float* qbase = qkv + (size_t)(b * 64) * 1536;

    for (int h = 0; h < HEADS; h++) {
        // load q,k natural + v natural into sS (all tf32-rounded)
        for (int idx = tid; idx < 1024; idx += 256) {
            int row = idx >> 4;
            int dg = (idx & 15) << 2;
            const float* src = qbase + (size_t)row * 1536 + h * 64 + dg;
            float4 qv = *(const float4*)(src);
            qv.x = tf32r(qv.x); qv.y = tf32r(qv.y); qv.z = tf32r(qv.z); qv.w = tf32r(qv.w);
            *(float4*)&qN[row * 68 + dg] = qv;
            float4 kv = *(const float4*)(src + 512);
            kv.x = tf32r(kv.x); kv.y = tf32r(kv.y); kv.z = tf32r(kv.z); kv.w = tf32r(kv.w);
            *(float4*)&kN[row * 68 + dg] = kv;
            float4 vv = *(const float4*)(src + 1024);
            vv.x = tf32r(vv.x); vv.y = tf32r(vv.y); vv.z = tf32r(vv.z); vv.w = tf32r(vv.w);
            *(float4*)&sS[row * 68 + dg] = vv;
        }
        __syncthreads();
        // transpose v: sS[j][d] -> vT[d][j]
        for (int idx = tid; idx < 4096; idx += 256) {
            int j = idx >> 6;
            int d = idx & 63;
            vT[d * 68 + j] = sS[j * 68 + d];
        }
        __syncthreads();

        // S = q @ k^T
        float acc[4][4];
#pragma unroll
        for (int i = 0; i < 4; i++)
#pragma unroll
            for (int j = 0; j < 4; j++) acc[i][j] = 0.f;
        {
            const float* aB = qN + (m0 + r) * 68 + cc;
#pragma unroll
            for (int k8 = 0; k8 < 8; k8++) {
                uint32_t af[4];
                const float* ap = aB + k8 * 8;
                af[0] = __float_as_uint(ap[0]);
                af[1] = __float_as_uint(ap[8 * 68]);
                af[2] = __float_as_uint(ap[4]);
                af[3] = __float_as_uint(ap[8 * 68 + 4]);
#pragma unroll
                for (int nt = 0; nt < 4; nt++) {
                    const float* bp = kN + (n0 + nt * 8 + r) * 68 + cc + k8 * 8;
                    uint32_t bf[2] = { __float_as_uint(bp[0]), __float_as_uint(bp[4]) };
                    mma_tf32(acc[nt], af, bf);
                }
            }
        }
        __syncthreads();   // everyone's v-transpose reads of sS done (above), safe to overwrite
        // logits = s*mult + bias  -> sS
#pragma unroll
        for (int nt = 0; nt < 4; nt++) {
            int col = n0 + nt * 8 + 2 * cc;
            int I0 = m0 + r, I1 = I0 + 8;
            sS[I0 * 68 + col]     = acc[nt][0] * sMult[I0 * 68 + col]     + relbias(sBias, I0, col, h);
            sS[I0 * 68 + col + 1] = acc[nt][1] * sMult[I0 * 68 + col + 1] + relbias(sBias, I0, col + 1, h);
            sS[I1 * 68 + col]     = acc[nt][2] * sMult[I1 * 68 + col]     + relbias(sBias, I1, col, h);
            sS[I1 * 68 + col + 1] = acc[nt][3] * sMult[I1 * 68 + col + 1] + relbias(sBias, I1, col + 1, h);
        }
        __syncthreads();

        // softmax rows of sS (probs tf32-rounded)
        for (int rr = w; rr < 64; rr += 8) {
            float x0 = sS[rr * 68 + lane];
            float x1 = sS[rr * 68 + lane + 32];
            float m = fmaxf(x0, x1);
#pragma unroll
            for (int o = 16; o; o >>= 1) m = fmaxf(m, __shfl_xor_sync(0xffffffffu, m, o));
            float e0 = expf(x0 - m), e1 = expf(x1 - m);
            float s = e0 + e1;
#pragma unroll
            for (int o = 16; o; o >>= 1) s += __shfl_xor_sync(0xffffffffu, s, o);
            float inv = 1.0f / s;
            sS[rr * 68 + lane] = tf32r(e0 * inv);
            sS[rr * 68 + lane + 32] = tf32r(e1 * inv);
        }
        __syncthreads();

        // O = P @ V   (B = vT rows = V columns)
        float oacc[4][4];
#pragma unroll
        for (int i = 0; i < 4; i++)
#pragma unroll
            for (int j = 0; j < 4; j++) oacc[i][j] = 0.f;
        {
            const float* aB = sS + (m0 + r) * 68 + cc;
#pragma unroll
            for (int k8 = 0; k8 < 8; k8++) {
                uint32_t af[4];
                const float* ap = aB + k8 * 8;
                af[0] = __float_as_uint(ap[0]);
                af[1] = __float_as_uint(ap[8 * 68]);
                af[2] = __float_as_uint(ap[4]);
                af[3] = __float_as_uint(ap[8 * 68 + 4]);
#pragma unroll
                for (int nt = 0; nt < 4; nt++) {
                    const float* bp = vT + (n0 + nt * 8 + r) * 68 + cc + k8 * 8;
                    uint32_t bf[2] = { __float_as_uint(bp[0]), __float_as_uint(bp[4]) };
                    mma_tf32(oacc[nt], af, bf);
                }
            }
        }
        // store O (tf32-rounded for the proj GEMM)
        float* ob = obuf + (size_t)(b * 64) * 512 + h * 64;
#pragma unroll
        for (int nt = 0; nt < 4; nt++) {
            int col = n0 + nt * 8 + 2 * cc;
            *(float2*)(ob + (size_t)(m0 + r) * 512 + col) =
                make_float2(tf32r(oacc[nt][0]), tf32r(oacc[nt][1]));
            *(float2*)(ob + (size_t)(m0 + r + 8) * 512 + col) =
                make_float2(tf32r(oacc[nt][2]), tf32r(oacc[nt][3]));
        }
        __syncthreads();
    }
}

// =====================================================================
extern "C" void kernel_launch(void* const* d_in, const int* in_sizes, int n_in,
                              void* d_out, int out_size)
{
    const float* x      = (const float*)d_in[0];
    const float* dino   = (const float*)d_in[1];
    const float* point  = (const float*)d_in[2];
    /* d_in[3] color_feature: unused by reference */
    const float* sdf    = (const float*)d_in[4];
    const float* normal = (const float*)d_in[5];
    const float* smask  = (const float*)d_in[6];
    const float* cmask  = (const float*)d_in[7];
    const float* wq     = (const float*)d_in[8];
    const float* bq     = (const float*)d_in[9];
    const float* wkv    = (const float*)d_in[10];
    const float* bkv    = (const float*)d_in[11];
    const float* rel    = (const float*)d_in[12];
    const float* wproj  = (const float*)d_in[13];
    const float* bproj  = (const float*)d_in[14];
    float* out = (float*)d_out;

    float *qkv, *mbuf, *obuf, *xr, *wr, *gb;
    cudaGetSymbolAddress((void**)&qkv, g_qkv);
    cudaGetSymbolAddress((void**)&mbuf, g_mult);
    cudaGetSymbolAddress((void**)&obuf, g_o);
    cudaGetSymbolAddress((void**)&xr, g_xr);
    cudaGetSymbolAddress((void**)&wr, g_wr);
    cudaGetSymbolAddress((void**)&gb, g_bias);

    const int smem_mult = SMEM_MULT_FLOATS * 4;
    const int smem_attn = SMEM_ATTN_FLOATS * 4;
    cudaFuncSetAttribute(mult_kernel, cudaFuncAttributeMaxDynamicSharedMemorySize, smem_mult);
    cudaFuncSetAttribute(attn_kernel, cudaFuncAttributeMaxDynamicSharedMemorySize, smem_attn);
    cudaFuncSetAttribute(gemm_tf32, cudaFuncAttributeMaxDynamicSharedMemorySize, SMEM_GEMM_BYTES);

    dim3 blk(256);

    // tf32 pre-round: x and weights (SCALE folded into wq/bq)
    round_kernel<<<1184, 256>>>(x, xr, (MROWS * DIM) / 4, 1.0f);
    round_kernel<<<128, 256>>>(wq, wr, (512 * 512) / 4, SCALE);
    round_kernel<<<128, 256>>>(wkv, wr + 512 * 512, (1024 * 512) / 4, 1.0f);
    round_kernel<<<128, 256>>>(wproj, wr + 1536 * 512, (512 * 512) / 4, 1.0f);
    bias_combine<<<6, 256>>>(bq, bkv, gb);

    // qkv = x @ [SCALE*wq | wkv]^T + [SCALE*bq | bkv]   (one merged GEMM)
    gemm_tf32<<<dim3(6, MROWS / 128), blk, SMEM_GEMM_BYTES>>>(
        xr, wr, gb, qkv, 1536, 1.0f);
    // correlation maps
    mult_kernel<<<NB, blk, smem_mult>>>(dino, point, sdf, normal, smask, cmask, mbuf);
    // attention (writes tf32-rounded o)
    attn_kernel<<<NB, blk, smem_attn>>>(mbuf, rel, qkv, obuf);
    // out = o @ wproj^T + bproj
    gemm_tf32<<<dim3(2, MROWS / 128), blk, SMEM_GEMM_BYTES>>>(
        obuf, wr + 1536 * 512, bproj, out, 512, 1.0f);
}

// round 6
// speedup vs baseline: 4.0110x; 1.5571x over previous
#include <cuda_runtime.h>
#include <cuda_fp16.h>
#include <math.h>
#include <stdint.h>

#define NTOK 64
#define DIM 512
#define HEADS 8
#define NB 2048
#define MROWS (NB * NTOK)   // 131072
#define SCALE 0.125f
#define KDIM 512

// ---------------- scratch (device globals; no allocation) ----------------
static __device__ __half g_qkvh[(size_t)MROWS * 1536];  // q(scaled)|k|v  (half)
static __device__ float  g_mult[(size_t)NB * NTOK * NTOK];
static __device__ __half g_oh[(size_t)MROWS * DIM];     // attn out (half)
static __device__ __half g_xh[(size_t)MROWS * DIM];     // x  (half)
static __device__ __half g_wh[(size_t)2048 * 512];      // wq*SCALE|wkv|wproj (half)
static __device__ float  g_bias[1536];                  // SCALE*bq | bkv

__device__ __forceinline__ uint32_t smem_u32(const void* p) {
    uint32_t a;
    asm("{ .reg .u64 t; cvta.to.shared.u64 t, %1; cvt.u32.u64 %0, t; }" : "=r"(a) : "l"(p));
    return a;
}
#define CP_ASYNC16(dst, src) \
    asm volatile("cp.async.cg.shared.global [%0], [%1], 16;" :: "r"(dst), "l"(src) : "memory")
#define CP_COMMIT() asm volatile("cp.async.commit_group;" ::: "memory")
#define CP_WAIT2()  asm volatile("cp.async.wait_group 2;" ::: "memory")

__device__ __forceinline__ void mma_f16(float* d, const uint32_t* a, const uint32_t* b) {
    asm volatile(
        "mma.sync.aligned.m16n8k16.row.col.f32.f16.f16.f32 "
        "{%0,%1,%2,%3}, {%4,%5,%6,%7}, {%8,%9}, {%0,%1,%2,%3};"
        : "+f"(d[0]), "+f"(d[1]), "+f"(d[2]), "+f"(d[3])
        : "r"(a[0]), "r"(a[1]), "r"(a[2]), "r"(a[3]), "r"(b[0]), "r"(b[1]));
}
__device__ __forceinline__ void mma_tf32(float* d, const uint32_t* a, const uint32_t* b) {
    asm volatile(
        "mma.sync.aligned.m16n8k8.row.col.f32.tf32.tf32.f32 "
        "{%0,%1,%2,%3}, {%4,%5,%6,%7}, {%8,%9}, {%0,%1,%2,%3};"
        : "+f"(d[0]), "+f"(d[1]), "+f"(d[2]), "+f"(d[3])
        : "r"(a[0]), "r"(a[1]), "r"(a[2]), "r"(a[3]), "r"(b[0]), "r"(b[1]));
}
__device__ __forceinline__ float tf32r(float x) {
    asm("cvt.rna.tf32.f32 %0, %0;" : "+f"(x));
    return x;
}

// ===================== fp32 -> fp16 conversion (optional scale) =====================
__global__ void conv_kernel(const float* __restrict__ in, __half* __restrict__ out,
                            int n4, float s)
{
    int i = blockIdx.x * blockDim.x + threadIdx.x;
    int stride = gridDim.x * blockDim.x;
    for (; i < n4; i += stride) {
        float4 v = ((const float4*)in)[i];
        __half2* o = (__half2*)out;
        o[2 * i]     = __floats2half2_rn(v.x * s, v.y * s);
        o[2 * i + 1] = __floats2half2_rn(v.z * s, v.w * s);
    }
}

__global__ void bias_combine(const float* __restrict__ bq, const float* __restrict__ bkv,
                             float* __restrict__ gb)
{
    int i = blockIdx.x * blockDim.x + threadIdx.x;
    if (i < 1536) gb[i] = (i < 512) ? bq[i] * SCALE : bkv[i - 512];
}

// =====================================================================
// fp16 mma GEMM:  C[m,n] = sum_k A[m,k]*B[n,k] + bias[n]
// A half [M,512], B half [N,512]; CTA 128x256, 8 warps (2m x 4n) of 64x64
// BK=64 halfs; 3-stage cp.async ring.  OUTH: 1 = half output, 0 = float.
// =====================================================================
#define BKH 64
#define HSTRIDE 72                              // halfs per smem row
#define STAGE_HALFS ((128 + 256) * HSTRIDE)     // 27648
#define STAGE_BYTES (STAGE_HALFS * 2)           // 55296
#define NSTAGE 3
#define SMEM_GEMM_BYTES (NSTAGE * STAGE_BYTES)  // 165888
#define NCHUNK (KDIM / BKH)                     // 8

template<int OUTH>
__global__ __launch_bounds__(256, 1)
void gemm_f16(const __half* __restrict__ A, const __half* __restrict__ B,
              const float* __restrict__ bias, void* __restrict__ Cv, long ldc)
{
    extern __shared__ char smc[];
    __half* smh = (__half*)smc;
    const int tid = threadIdx.x;
    const int lane = tid & 31;
    const int wid = tid >> 5;
    const int warp_m = wid & 1;
    const int warp_n = wid >> 1;
    const long m0 = (long)blockIdx.y * 128;
    const long n0 = (long)blockIdx.x * 256;

    const __half* Ag = A + m0 * KDIM;
    const __half* Bg = B + n0 * KDIM;
    const uint32_t sb = smem_u32(smc);

    auto copy_chunk = [&](int chunk, int s) {
        const int k0 = chunk * BKH;
        const uint32_t dstA = sb + s * STAGE_BYTES;
        const uint32_t dstB = dstA + 128 * HSTRIDE * 2;
#pragma unroll
        for (int i = 0; i < 4; i++) {
            int idx = tid + i * 256;          // 0..1023
            int row = idx >> 3, q = idx & 7;  // q: 16B (=8 halfs) chunk
            CP_ASYNC16(dstA + row * (HSTRIDE * 2) + q * 16,
                       Ag + (long)row * KDIM + k0 + q * 8);
        }
#pragma unroll
        for (int i = 0; i < 8; i++) {
            int idx = tid + i * 256;          // 0..2047
            int row = idx >> 3, q = idx & 7;
            CP_ASYNC16(dstB + row * (HSTRIDE * 2) + q * 16,
                       Bg + (long)row * KDIM + k0 + q * 8);
        }
        CP_COMMIT();
    };

    float acc[4][8][4];
#pragma unroll
    for (int mt = 0; mt < 4; mt++)
#pragma unroll
        for (int nt = 0; nt < 8; nt++)
#pragma unroll
            for (int e = 0; e < 4; e++) acc[mt][nt][e] = 0.f;

    copy_chunk(0, 0);
    copy_chunk(1, 1);
    copy_chunk(2, 2);

    const int r = lane >> 2;
    const int cc = lane & 3;

    for (int c = 0; c < NCHUNK; c++) {
        const int s = c % NSTAGE;
        CP_WAIT2();
        __syncthreads();

        const __half* sA = smh + s * STAGE_HALFS;
        const __half* sB = sA + 128 * HSTRIDE;
        const __half* aB = sA + (warp_m * 64 + r) * HSTRIDE + 2 * cc;
        const __half* bB = sB + (warp_n * 64 + r) * HSTRIDE + 2 * cc;

#pragma unroll
        for (int k16 = 0; k16 < 4; k16++) {
            uint32_t af[4][4];
#pragma unroll
            for (int mt = 0; mt < 4; mt++) {
                const __half* ap = aB + mt * 16 * HSTRIDE + k16 * 16;
                af[mt][0] = *(const uint32_t*)(ap);
                af[mt][1] = *(const uint32_t*)(ap + 8 * HSTRIDE);
                af[mt][2] = *(const uint32_t*)(ap + 8);
                af[mt][3] = *(const uint32_t*)(ap + 8 * HSTRIDE + 8);
            }
            uint32_t bf[8][2];
#pragma unroll
            for (int nt = 0; nt < 8; nt++) {
                const __half* bp = bB + nt * 8 * HSTRIDE + k16 * 16;
                bf[nt][0] = *(const uint32_t*)(bp);
                bf[nt][1] = *(const uint32_t*)(bp + 8);
            }
#pragma unroll
            for (int mt = 0; mt < 4; mt++)
#pragma unroll
                for (int nt = 0; nt < 8; nt++)
                    mma_f16(acc[mt][nt], af[mt], bf[nt]);
        }
        __syncthreads();
        if (c + 3 < NCHUNK) copy_chunk(c + 3, s);
        else CP_COMMIT();
    }

    // ---- epilogue: bias add in fp32, stage via smem, coalesced stores ----
    if (OUTH) {
        __half* se = smh;                     // stride 264 halfs
        const int row0 = warp_m * 64;
        const int col0 = warp_n * 64;
#pragma unroll
        for (int mt = 0; mt < 4; mt++)
#pragma unroll
            for (int nt = 0; nt < 8; nt++) {
                int rr = row0 + mt * 16 + r;
                int cb = col0 + nt * 8 + 2 * cc;
                float2 bv = *(const float2*)(bias + n0 + cb);
                *(__half2*)(se + rr * 264 + cb) =
                    __floats2half2_rn(acc[mt][nt][0] + bv.x, acc[mt][nt][1] + bv.y);
                *(__half2*)(se + (rr + 8) * 264 + cb) =
                    __floats2half2_rn(acc[mt][nt][2] + bv.x, acc[mt][nt][3] + bv.y);
            }
        __syncthreads();
        __half* Ch = (__half*)Cv;
#pragma unroll
        for (int i = 0; i < 16; i++) {
            int idx = tid + i * 256;          // 0..4095 chunks of 8 halfs
            int row = idx >> 5;
            int c8 = (idx & 31) * 8;
            float4 v = *(const float4*)(se + row * 264 + c8);
            *(float4*)(Ch + (m0 + row) * ldc + n0 + c8) = v;
        }
    } else {
        float* se = (float*)smc;              // stride 264 floats
        const int row0 = warp_m * 64;
        const int col0 = warp_n * 64;
#pragma unroll
        for (int mt = 0; mt < 4; mt++)
#pragma unroll
            for (int nt = 0; nt < 8; nt++) {
                int rr = row0 + mt * 16 + r;
                int cb = col0 + nt * 8 + 2 * cc;
                float2 bv = *(const float2*)(bias + n0 + cb);
                *(float2*)(se + rr * 264 + cb) =
                    make_float2(acc[mt][nt][0] + bv.x, acc[mt][nt][1] + bv.y);
                *(float2*)(se + (rr + 8) * 264 + cb) =
                    make_float2(acc[mt][nt][2] + bv.x, acc[mt][nt][3] + bv.y);
            }
        __syncthreads();
        float* Cf = (float*)Cv;
#pragma unroll
        for (int i = 0; i < 32; i++) {
            int idx = tid + i * 256;
            int row = idx >> 6;
            int c4 = (idx & 63) * 4;
            float4 v = *(const float4*)(se + row * 264 + c4);
            *(float4*)(Cf + (m0 + row) * ldc + n0 + c4) = v;
        }
    }
}

// =====================================================================
// Correlation-map kernel (unchanged from R4): tf32 mma dino Gram
// =====================================================================
#define DSTRIDE 100
#define SMEM_MULT_FLOATS (2*64*DSTRIDE + 64*68 + 64*17 + 64 + 64 + 192 + 192 + 64 + 512)

__global__ __launch_bounds__(256)
void mult_kernel(const float* __restrict__ dino, const float* __restrict__ point,
                 const float* __restrict__ sdf, const float* __restrict__ normal,
                 const float* __restrict__ smask, const float* __restrict__ cmask,
                 float* __restrict__ mout)
{
    extern __shared__ float sm[];
    float* sD    = sm;
    float* sG    = sD + 2 * 64 * DSTRIDE;
    float* sSF   = sG + 64 * 68;
    float* rnD   = sSF + 64 * 17;
    float* rnS   = rnD + 64;
    float* sp    = rnS + 64;
    float* sn    = sp + 192;
    float* scode = sn + 192;
    float* scl   = scode + 64;

    const int b = blockIdx.x;
    const int tid = threadIdx.x;
    const int lane = tid & 31, w = tid >> 5;
    const int r = lane >> 2, cc = lane & 3;
    const int m0 = (w & 3) * 16, n0 = (w >> 2) * 32;

    const float* sg = sdf + (size_t)b * 64 * 16;
    {
        int row = tid >> 2;
        int kg = (tid & 3) * 4;
        float4 v = *(const float4*)(sg + row * 16 + kg);
        sSF[row * 17 + kg + 0] = v.x;
        sSF[row * 17 + kg + 1] = v.y;
        sSF[row * 17 + kg + 2] = v.z;
        sSF[row * 17 + kg + 3] = v.w;
    }
    if (tid < 192) {
        sp[tid] = point[(size_t)b * 192 + tid];
        sn[tid] = normal[(size_t)b * 192 + tid];
    }
    if (tid < 64)
        scode[tid] = (smask[(size_t)b * 64 + tid] < 0.1f) ? 1.f : 2.f;
    for (int idx = tid; idx < 512; idx += 256)
        scl[idx] = cmask[(size_t)b * 512 + idx];

    const float* dg = dino + (size_t)b * 64 * 384;
    auto load_chunk = [&](int kc, int buf) {
        float* dst = sD + buf * 64 * DSTRIDE;
        const int k0 = kc * 96;
#pragma unroll
        for (int i = 0; i < 6; i++) {
            int idx = tid + i * 256;
            int row = idx / 24;
            int q = idx % 24;
            float4 v = *(const float4*)(dg + row * 384 + k0 + q * 4);
            v.x = tf32r(v.x); v.y = tf32r(v.y); v.z = tf32r(v.z); v.w = tf32r(v.w);
            *(float4*)(dst + row * DSTRIDE + q * 4) = v;
        }
    };

    float gacc[4][4];
#pragma unroll
    for (int i = 0; i < 4; i++)
#pragma unroll
        for (int j = 0; j < 4; j++) gacc[i][j] = 0.f;

    load_chunk(0, 0);
    __syncthreads();
    for (int c = 0; c < 4; c++) {
        if (c + 1 < 4) load_chunk(c + 1, (c + 1) & 1);
        const float* buf = sD + (c & 1) * 64 * DSTRIDE;
        const float* aB = buf + (m0 + r) * DSTRIDE + cc;
#pragma unroll
        for (int k8 = 0; k8 < 12; k8++) {
            uint32_t af[4];
            const float* ap = aB + k8 * 8;
            af[0] = __float_as_uint(ap[0]);
            af[1] = __float_as_uint(ap[8 * DSTRIDE]);
            af[2] = __float_as_uint(ap[4]);
            af[3] = __float_as_uint(ap[8 * DSTRIDE + 4]);
#pragma unroll
            for (int nt = 0; nt < 4; nt++) {
                const float* bp = buf + (n0 + nt * 8 + r) * DSTRIDE + cc + k8 * 8;
                uint32_t bf[2] = { __float_as_uint(bp[0]), __float_as_uint(bp[4]) };
                mma_tf32(gacc[nt], af, bf);
            }
        }
        __syncthreads();
    }
#pragma unroll
    for (int nt = 0; nt < 4; nt++) {
        int col = n0 + nt * 8 + 2 * cc;
        int I0 = m0 + r, I1 = I0 + 8;
        sG[I0 * 68 + col]     = gacc[nt][0];
        sG[I0 * 68 + col + 1] = gacc[nt][1];
        sG[I1 * 68 + col]     = gacc[nt][2];
        sG[I1 * 68 + col + 1] = gacc[nt][3];
    }
    __syncthreads();

    if (tid < 64) {
        float nn = fminf(fmaxf(sqrtf(fmaxf(sG[tid * 68 + tid], 0.f)), 1e-20f), 1e10f);
        rnD[tid] = 1.0f / nn;
        float s2 = 0.f;
#pragma unroll
        for (int k = 0; k < 16; k++) { float v = sSF[tid * 17 + k]; s2 += v * v; }
        nn = fminf(fmaxf(sqrtf(s2), 1e-20f), 1e10f);
        rnS[tid] = 1.0f / nn;
    }
    __syncthreads();

    const int tx = tid & 15, ty = tid >> 4;
    float sacc[4][4];
#pragma unroll
    for (int i = 0; i < 4; i++)
#pragma unroll
        for (int j = 0; j < 4; j++) sacc[i][j] = 0.f;
#pragma unroll
    for (int c = 0; c < 16; c++) {
        float aS[4], bS[4];
#pragma unroll
        for (int i = 0; i < 4; i++) aS[i] = sSF[(ty * 4 + i) * 17 + c];
#pragma unroll
        for (int j = 0; j < 4; j++) bS[j] = sSF[(tx * 4 + j) * 17 + c];
#pragma unroll
        for (int i = 0; i < 4; i++)
#pragma unroll
            for (int j = 0; j < 4; j++)
                sacc[i][j] += aS[i] * bS[j];
    }

    float* mrow = mout + (size_t)b * 4096;
#pragma unroll
    for (int i = 0; i < 4; i++) {
        int I = ty * 4 + i;
        float res[4];
#pragma unroll
        for (int j = 0; j < 4; j++) {
            int J = tx * 4 + j;
            float dmap = fminf(fmaxf(sG[I * 68 + J] * rnD[I] * rnD[J], 0.f), 1e10f);
            float smap = 1.f - fminf(fmaxf(sacc[i][j] * rnS[I] * rnS[J], 0.f), 1.f);
            float P1 = 0.f, P2 = 0.f;
#pragma unroll
            for (int d = 0; d < 3; d++) {
                float diff = sp[I * 3 + d] - sp[J * 3 + d];
                P1 += diff * sn[I * 3 + d];
                P2 += diff * sn[J * 3 + d];
            }
            float plane = expf(-0.5f * (fabsf(P1) + fabsf(P2)));
            float mm = (scode[I] * scode[J] == 2.f) ? 1.f : 0.2f;
            float ccv = 0.f;
#pragma unroll
            for (int c = 0; c < 8; c++) ccv += scl[I * 8 + c] * scl[J * 8 + c];
            res[j] = dmap * smap * plane * ccv * mm;
        }
        *(float4*)(mrow + I * 64 + tx * 4) = make_float4(res[0], res[1], res[2], res[3]);
    }
}

// =====================================================================
// Attention kernel: fp16 mma for QK^T and P@V; fp32 softmax
// =====================================================================
// smem carve (bytes): qH 9216 | kH 9216 | vT 8448 | pH 9216 | sS 17408 |
//                     sMult 17408 | sBias 7200  => 78112
#define ATTN_QH    0
#define ATTN_KH    (ATTN_QH + 64*72*2)
#define ATTN_VT    (ATTN_KH + 64*72*2)
#define ATTN_PH    (ATTN_VT + 64*66*2)
#define ATTN_SS    (ATTN_PH + 64*72*2)
#define ATTN_MULT  (ATTN_SS + 64*68*4)
#define ATTN_BIAS  (ATTN_MULT + 64*68*4)
#define SMEM_ATTN_BYTES (ATTN_BIAS + 1800*4)

__device__ __forceinline__ float relbias(const float* sBias, int I, int J, int h) {
    int dy = (I >> 3) - (J >> 3) + 7;
    int dx = (I & 7) - (J & 7) + 7;
    return sBias[(dy * 15 + dx) * 8 + h];
}

__global__ __launch_bounds__(256)
void attn_kernel(const float* __restrict__ mult, const float* __restrict__ rel_table,
                 const __half* __restrict__ qkv, __half* __restrict__ obuf)
{
    extern __shared__ char smc[];
    __half* qH    = (__half*)(smc + ATTN_QH);    // [64][72]
    __half* kH    = (__half*)(smc + ATTN_KH);    // [64][72]
    __half* vT    = (__half*)(smc + ATTN_VT);    // [64][66] transposed
    __half* pH    = (__half*)(smc + ATTN_PH);    // [64][72] probs
    float*  sS    = (float*) (smc + ATTN_SS);    // [64][68] logits
    float*  sMult = (float*) (smc + ATTN_MULT);  // [64][68]
    float*  sBias = (float*) (smc + ATTN_BIAS);  // [225*8]

    const int b = blockIdx.x;
    const int tid = threadIdx.x;
    const int lane = tid & 31, w = tid >> 5;
    const int r = lane >> 2, cc = lane & 3;
    const int m0 = (w & 3) * 16, n0 = (w >> 2) * 32;

    for (int idx = tid; idx < 1024; idx += 256) {
        int row = idx >> 4;
        int c4 = (idx & 15) * 4;
        float4 v = *(const float4*)(mult + (size_t)b * 4096 + row * 64 + c4);
        *(float4*)(sMult + row * 68 + c4) = v;
    }
    for (int i = tid; i < 1800; i += 256)
        sBias[i] = rel_table[i];

    const __half* qbase = qkv + (size_t)(b * 64) * 1536;

    for (int h = 0; h < HEADS; h++) {
        // load q,k (natural) + v (transposed) — all half
        for (int idx = tid; idx < 1024; idx += 256) {
            int row = idx >> 4;
            int dg = (idx & 15) << 2;                  // 4 halfs
            const __half* src = qbase + (size_t)row * 1536 + h * 64 + dg;
            *(uint2*)(qH + row * 72 + dg) = *(const uint2*)(src);
            *(uint2*)(kH + row * 72 + dg) = *(const uint2*)(src + 512);
            __half vh[4];
            *(uint2*)vh = *(const uint2*)(src + 1024);
            vT[(dg + 0) * 66 + row] = vh[0];
            vT[(dg + 1) * 66 + row] = vh[1];
            vT[(dg + 2) * 66 + row] = vh[2];
            vT[(dg + 3) * 66 + row] = vh[3];
        }
        __syncthreads();

        // S = q @ k^T  (fp16 mma, fp32 acc)
        float acc[4][4];
#pragma unroll
        for (int i = 0; i < 4; i++)
#pragma unroll
            for (int j = 0; j < 4; j++) acc[i][j] = 0.f;
        {
            const __half* aB = qH + (m0 + r) * 72 + 2 * cc;
#pragma unroll
            for (int k16 = 0; k16 < 4; k16++) {
                uint32_t af[4];
                const __half* ap = aB + k16 * 16;
                af[0] = *(const uint32_t*)(ap);
                af[1] = *(const uint32_t*)(ap + 8 * 72);
                af[2] = *(const uint32_t*)(ap + 8);
                af[3] = *(const uint32_t*)(ap + 8 * 72 + 8);
#pragma unroll
                for (int nt = 0; nt < 4; nt++) {
                    const __half* bp = kH + (n0 + nt * 8 + r) * 72 + 2 * cc + k16 * 16;
                    uint32_t bf[2] = { *(const uint32_t*)(bp), *(const uint32_t*)(bp + 8) };
                    mma_f16(acc[nt], af, bf);
                }
            }
        }
        // logits = s*mult + bias -> sS (fp32)
#pragma unroll
        for (int nt = 0; nt < 4; nt++) {
            int col = n0 + nt * 8 + 2 * cc;
            int I0 = m0 + r, I1 = I0 + 8;
            sS[I0 * 68 + col]     = acc[nt][0] * sMult[I0 * 68 + col]     + relbias(sBias, I0, col, h);
            sS[I0 * 68 + col + 1] = acc[nt][1] * sMult[I0 * 68 + col + 1] + relbias(sBias, I0, col + 1, h);
            sS[I1 * 68 + col]     = acc[nt][2] * sMult[I1 * 68 + col]     + relbias(sBias, I1, col, h);
            sS[I1 * 68 + col + 1] = acc[nt][3] * sMult[I1 * 68 + col + 1] + relbias(sBias, I1, col + 1, h);
        }
        __syncthreads();

        // softmax rows (fp32) -> pH (half)
        for (int rr = w; rr < 64; rr += 8) {
            float x0 = sS[rr * 68 + lane];
            float x1 = sS[rr * 68 + lane + 32];
            float m = fmaxf(x0, x1);
#pragma unroll
            for (int o = 16; o; o >>= 1) m = fmaxf(m, __shfl_xor_sync(0xffffffffu, m, o));
            float e0 = expf(x0 - m), e1 = expf(x1 - m);
            float s = e0 + e1;
#pragma unroll
            for (int o = 16; o; o >>= 1) s += __shfl_xor_sync(0xffffffffu, s, o);
            float inv = 1.0f / s;
            pH[rr * 72 + lane]      = __float2half(e0 * inv);
            pH[rr * 72 + lane + 32] = __float2half(e1 * inv);
        }
        __syncthreads();

        // O = P @ V  (A = pH, B = vT)
        float oacc[4][4];
#pragma unroll
        for (int i = 0; i < 4; i++)
#pragma unroll
            for (int j = 0; j < 4; j++) oacc[i][j] = 0.f;
        {
            const __half* aB = pH + (m0 + r) * 72 + 2 * cc;
#pragma unroll
            for (int k16 = 0; k16 < 4; k16++) {
                uint32_t af[4];
                const __half* ap = aB + k16 * 16;
                af[0] = *(const uint32_t*)(ap);
                af[1] = *(const uint32_t*)(ap + 8 * 72);
                af[2] = *(const uint32_t*)(ap + 8);
                af[3] = *(const uint32_t*)(ap + 8 * 72 + 8);
#pragma unroll
                for (int nt = 0; nt < 4; nt++) {
                    const __half* bp = vT + (n0 + nt * 8 + r) * 66 + 2 * cc + k16 * 16;
                    uint32_t bf[2] = { *(const uint32_t*)(bp), *(const uint32_t*)(bp + 8) };
                    mma_f16(oacc[nt], af, bf);
                }
            }
        }
        // store O (half)
        __half* ob = obuf + (size_t)(b * 64) * 512 + h * 64;
#pragma unroll
        for (int nt = 0; nt < 4; nt++) {
            int col = n0 + nt * 8 + 2 * cc;
            *(__half2*)(ob + (size_t)(m0 + r) * 512 + col) =
                __floats2half2_rn(oacc[nt][0], oacc[nt][1]);
            *(__half2*)(ob + (size_t)(m0 + r + 8) * 512 + col) =
                __floats2half2_rn(oacc[nt][2], oacc[nt][3]);
        }
        __syncthreads();
    }
}

// =====================================================================
extern "C" void kernel_launch(void* const* d_in, const int* in_sizes, int n_in,
                              void* d_out, int out_size)
{
    const float* x      = (const float*)d_in[0];
    const float* dino   = (const float*)d_in[1];
    const float* point  = (const float*)d_in[2];
    /* d_in[3] color_feature: unused by reference */
    const float* sdf    = (const float*)d_in[4];
    const float* normal = (const float*)d_in[5];
    const float* smask  = (const float*)d_in[6];
    const float* cmask  = (const float*)d_in[7];
    const float* wq     = (const float*)d_in[8];
    const float* bq     = (const float*)d_in[9];
    const float* wkv    = (const float*)d_in[10];
    const float* bkv    = (const float*)d_in[11];
    const float* rel    = (const float*)d_in[12];
    const float* wproj  = (const float*)d_in[13];
    const float* bproj  = (const float*)d_in[14];
    float* out = (float*)d_out;

    __half *qkvh, *oh, *xh, *wh;
    float *mbuf, *gb;
    cudaGetSymbolAddress((void**)&qkvh, g_qkvh);
    cudaGetSymbolAddress((void**)&mbuf, g_mult);
    cudaGetSymbolAddress((void**)&oh, g_oh);
    cudaGetSymbolAddress((void**)&xh, g_xh);
    cudaGetSymbolAddress((void**)&wh, g_wh);
    cudaGetSymbolAddress((void**)&gb, g_bias);

    const int smem_mult = SMEM_MULT_FLOATS * 4;
    cudaFuncSetAttribute(mult_kernel, cudaFuncAttributeMaxDynamicSharedMemorySize, smem_mult);
    cudaFuncSetAttribute(attn_kernel, cudaFuncAttributeMaxDynamicSharedMemorySize, SMEM_ATTN_BYTES);
    cudaFuncSetAttribute(gemm_f16<1>, cudaFuncAttributeMaxDynamicSharedMemorySize, SMEM_GEMM_BYTES);
    cudaFuncSetAttribute(gemm_f16<0>, cudaFuncAttributeMaxDynamicSharedMemorySize, SMEM_GEMM_BYTES);

    dim3 blk(256);

    // fp16 conversion: x and weights (SCALE folded into wq/bq)
    conv_kernel<<<1184, 256>>>(x, xh, (MROWS * DIM) / 4, 1.0f);
    conv_kernel<<<128, 256>>>(wq, wh, (512 * 512) / 4, SCALE);
    conv_kernel<<<128, 256>>>(wkv, wh + 512 * 512, (1024 * 512) / 4, 1.0f);
    conv_kernel<<<128, 256>>>(wproj, wh + 1536 * 512, (512 * 512) / 4, 1.0f);
    bias_combine<<<6, 256>>>(bq, bkv, gb);

    // qkv = x @ [SCALE*wq | wkv]^T + [SCALE*bq | bkv]  (half out)
    gemm_f16<1><<<dim3(6, MROWS / 128), blk, SMEM_GEMM_BYTES>>>(
        xh, wh, gb, qkvh, 1536);
    // correlation maps
    mult_kernel<<<NB, blk, smem_mult>>>(dino, point, sdf, normal, smask, cmask, mbuf);
    // attention (half in, half out)
    attn_kernel<<<NB, blk, SMEM_ATTN_BYTES>>>(mbuf, rel, qkvh, oh);
    // out = o @ wproj^T + bproj  (float out)
    gemm_f16<0><<<dim3(2, MROWS / 128), blk, SMEM_GEMM_BYTES>>>(
        oh, wh + 1536 * 512, bproj, out, 512);
}

// round 7
// speedup vs baseline: 4.8941x; 1.2202x over previous
#include <cuda_runtime.h>
#include <cuda_fp16.h>
#include <math.h>
#include <stdint.h>

#define NTOK 64
#define DIM 512
#define HEADS 8
#define NB 2048
#define MROWS (NB * NTOK)   // 131072
#define SCALE 0.125f
#define KDIM 512

// ---------------- scratch (device globals; no allocation) ----------------
static __device__ __half g_qkvh[(size_t)MROWS * 1536];  // q(scaled)|k|v  (half)
static __device__ float  g_mult[(size_t)NB * NTOK * NTOK];
static __device__ __half g_oh[(size_t)MROWS * DIM];     // attn out (half)
static __device__ __half g_xh[(size_t)MROWS * DIM];     // x  (half)
static __device__ __half g_wh[(size_t)2048 * 512];      // wq*SCALE|wkv|wproj (half)
static __device__ float  g_bias[1536];                  // SCALE*bq | bkv

__device__ __forceinline__ uint32_t smem_u32(const void* p) {
    uint32_t a;
    asm("{ .reg .u64 t; cvta.to.shared.u64 t, %1; cvt.u32.u64 %0, t; }" : "=r"(a) : "l"(p));
    return a;
}
#define CP_ASYNC16(dst, src) \
    asm volatile("cp.async.cg.shared.global [%0], [%1], 16;" :: "r"(dst), "l"(src) : "memory")
#define CP_COMMIT() asm volatile("cp.async.commit_group;" ::: "memory")
#define CP_WAIT2()  asm volatile("cp.async.wait_group 2;" ::: "memory")

#define LDSM_X2T(r0, r1, a) \
    asm volatile("ldmatrix.sync.aligned.m8n8.x2.trans.shared.b16 {%0,%1}, [%2];" \
                 : "=r"(r0), "=r"(r1) : "r"(a))

__device__ __forceinline__ void mma_f16(float* d, const uint32_t* a, const uint32_t* b) {
    asm volatile(
        "mma.sync.aligned.m16n8k16.row.col.f32.f16.f16.f32 "
        "{%0,%1,%2,%3}, {%4,%5,%6,%7}, {%8,%9}, {%0,%1,%2,%3};"
        : "+f"(d[0]), "+f"(d[1]), "+f"(d[2]), "+f"(d[3])
        : "r"(a[0]), "r"(a[1]), "r"(a[2]), "r"(a[3]), "r"(b[0]), "r"(b[1]));
}

// ===================== fp32 -> fp16 conversion (optional scale) =====================
__global__ void conv_kernel(const float* __restrict__ in, __half* __restrict__ out,
                            int n4, float s)
{
    int i = blockIdx.x * blockDim.x + threadIdx.x;
    int stride = gridDim.x * blockDim.x;
    for (; i < n4; i += stride) {
        float4 v = ((const float4*)in)[i];
        __half2* o = (__half2*)out;
        o[2 * i]     = __floats2half2_rn(v.x * s, v.y * s);
        o[2 * i + 1] = __floats2half2_rn(v.z * s, v.w * s);
    }
}

__global__ void bias_combine(const float* __restrict__ bq, const float* __restrict__ bkv,
                             float* __restrict__ gb)
{
    int i = blockIdx.x * blockDim.x + threadIdx.x;
    if (i < 1536) gb[i] = (i < 512) ? bq[i] * SCALE : bkv[i - 512];
}

// =====================================================================
// fp16 mma GEMM (unchanged from R6): C = A @ B^T + bias
// =====================================================================
#define BKH 64
#define HSTRIDE 72
#define STAGE_HALFS ((128 + 256) * HSTRIDE)
#define STAGE_BYTES (STAGE_HALFS * 2)
#define NSTAGE 3
#define SMEM_GEMM_BYTES (NSTAGE * STAGE_BYTES)
#define NCHUNK (KDIM / BKH)

template<int OUTH>
__global__ __launch_bounds__(256, 1)
void gemm_f16(const __half* __restrict__ A, const __half* __restrict__ B,
              const float* __restrict__ bias, void* __restrict__ Cv, long ldc)
{
    extern __shared__ char smc[];
    __half* smh = (__half*)smc;
    const int tid = threadIdx.x;
    const int lane = tid & 31;
    const int wid = tid >> 5;
    const int warp_m = wid & 1;
    const int warp_n = wid >> 1;
    const long m0 = (long)blockIdx.y * 128;
    const long n0 = (long)blockIdx.x * 256;

    const __half* Ag = A + m0 * KDIM;
    const __half* Bg = B + n0 * KDIM;
    const uint32_t sb = smem_u32(smc);

    auto copy_chunk = [&](int chunk, int s) {
        const int k0 = chunk * BKH;
        const uint32_t dstA = sb + s * STAGE_BYTES;
        const uint32_t dstB = dstA + 128 * HSTRIDE * 2;
#pragma unroll
        for (int i = 0; i < 4; i++) {
            int idx = tid + i * 256;
            int row = idx >> 3, q = idx & 7;
            CP_ASYNC16(dstA + row * (HSTRIDE * 2) + q * 16,
                       Ag + (long)row * KDIM + k0 + q * 8);
        }
#pragma unroll
        for (int i = 0; i < 8; i++) {
            int idx = tid + i * 256;
            int row = idx >> 3, q = idx & 7;
            CP_ASYNC16(dstB + row * (HSTRIDE * 2) + q * 16,
                       Bg + (long)row * KDIM + k0 + q * 8);
        }
        CP_COMMIT();
    };

    float acc[4][8][4];
#pragma unroll
    for (int mt = 0; mt < 4; mt++)
#pragma unroll
        for (int nt = 0; nt < 8; nt++)
#pragma unroll
            for (int e = 0; e < 4; e++) acc[mt][nt][e] = 0.f;

    copy_chunk(0, 0);
    copy_chunk(1, 1);
    copy_chunk(2, 2);

    const int r = lane >> 2;
    const int cc = lane & 3;

    for (int c = 0; c < NCHUNK; c++) {
        const int s = c % NSTAGE;
        CP_WAIT2();
        __syncthreads();

        const __half* sA = smh + s * STAGE_HALFS;
        const __half* sB = sA + 128 * HSTRIDE;
        const __half* aB = sA + (warp_m * 64 + r) * HSTRIDE + 2 * cc;
        const __half* bB = sB + (warp_n * 64 + r) * HSTRIDE + 2 * cc;

#pragma unroll
        for (int k16 = 0; k16 < 4; k16++) {
            uint32_t af[4][4];
#pragma unroll
            for (int mt = 0; mt < 4; mt++) {
                const __half* ap = aB + mt * 16 * HSTRIDE + k16 * 16;
                af[mt][0] = *(const uint32_t*)(ap);
                af[mt][1] = *(const uint32_t*)(ap + 8 * HSTRIDE);
                af[mt][2] = *(const uint32_t*)(ap + 8);
                af[mt][3] = *(const uint32_t*)(ap + 8 * HSTRIDE + 8);
            }
            uint32_t bf[8][2];
#pragma unroll
            for (int nt = 0; nt < 8; nt++) {
                const __half* bp = bB + nt * 8 * HSTRIDE + k16 * 16;
                bf[nt][0] = *(const uint32_t*)(bp);
                bf[nt][1] = *(const uint32_t*)(bp + 8);
            }
#pragma unroll
            for (int mt = 0; mt < 4; mt++)
#pragma unroll
                for (int nt = 0; nt < 8; nt++)
                    mma_f16(acc[mt][nt], af[mt], bf[nt]);
        }
        __syncthreads();
        if (c + 3 < NCHUNK) copy_chunk(c + 3, s);
        else CP_COMMIT();
    }

    if (OUTH) {
        __half* se = smh;
        const int row0 = warp_m * 64;
        const int col0 = warp_n * 64;
#pragma unroll
        for (int mt = 0; mt < 4; mt++)
#pragma unroll
            for (int nt = 0; nt < 8; nt++) {
                int rr = row0 + mt * 16 + r;
                int cb = col0 + nt * 8 + 2 * cc;
                float2 bv = *(const float2*)(bias + n0 + cb);
                *(__half2*)(se + rr * 264 + cb) =
                    __floats2half2_rn(acc[mt][nt][0] + bv.x, acc[mt][nt][1] + bv.y);
                *(__half2*)(se + (rr + 8) * 264 + cb) =
                    __floats2half2_rn(acc[mt][nt][2] + bv.x, acc[mt][nt][3] + bv.y);
            }
        __syncthreads();
        __half* Ch = (__half*)Cv;
#pragma unroll
        for (int i = 0; i < 16; i++) {
            int idx = tid + i * 256;
            int row = idx >> 5;
            int c8 = (idx & 31) * 8;
            float4 v = *(const float4*)(se + row * 264 + c8);
            *(float4*)(Ch + (m0 + row) * ldc + n0 + c8) = v;
        }
    } else {
        float* se = (float*)smc;
        const int row0 = warp_m * 64;
        const int col0 = warp_n * 64;
#pragma unroll
        for (int mt = 0; mt < 4; mt++)
#pragma unroll
            for (int nt = 0; nt < 8; nt++) {
                int rr = row0 + mt * 16 + r;
                int cb = col0 + nt * 8 + 2 * cc;
                float2 bv = *(const float2*)(bias + n0 + cb);
                *(float2*)(se + rr * 264 + cb) =
                    make_float2(acc[mt][nt][0] + bv.x, acc[mt][nt][1] + bv.y);
                *(float2*)(se + (rr + 8) * 264 + cb) =
                    make_float2(acc[mt][nt][2] + bv.x, acc[mt][nt][3] + bv.y);
            }
        __syncthreads();
        float* Cf = (float*)Cv;
#pragma unroll
        for (int i = 0; i < 32; i++) {
            int idx = tid + i * 256;
            int row = idx >> 6;
            int c4 = (idx & 63) * 4;
            float4 v = *(const float4*)(se + row * 264 + c4);
            *(float4*)(Cf + (m0 + row) * ldc + n0 + c4) = v;
        }
    }
}

// =====================================================================
// Correlation-map kernel: fp16 mma dino Gram (K=96 chunks, double-buffered)
// =====================================================================
#define MH_STRIDE 104
#define MK_D   0
#define MK_G   (MK_D + 2*64*MH_STRIDE*2)     // f32 [64][68]
#define MK_SF  (MK_G + 64*68*4)              // f32 [64][17]
#define MK_RND (MK_SF + 64*17*4)
#define MK_RNS (MK_RND + 256)
#define MK_SP  (MK_RNS + 256)
#define MK_SN  (MK_SP + 768)
#define MK_SC  (MK_SN + 768)
#define MK_SCL (MK_SC + 256)
#define SMEM_MULT_BYTES (MK_SCL + 2048)

__global__ __launch_bounds__(256)
void mult_kernel(const float* __restrict__ dino, const float* __restrict__ point,
                 const float* __restrict__ sdf, const float* __restrict__ normal,
                 const float* __restrict__ smask, const float* __restrict__ cmask,
                 float* __restrict__ mout)
{
    extern __shared__ char smc[];
    __half* sDh  = (__half*)(smc + MK_D);
    float* sG    = (float*)(smc + MK_G);
    float* sSF   = (float*)(smc + MK_SF);
    float* rnD   = (float*)(smc + MK_RND);
    float* rnS   = (float*)(smc + MK_RNS);
    float* sp    = (float*)(smc + MK_SP);
    float* sn    = (float*)(smc + MK_SN);
    float* scode = (float*)(smc + MK_SC);
    float* scl   = (float*)(smc + MK_SCL);

    const int b = blockIdx.x;
    const int tid = threadIdx.x;
    const int lane = tid & 31, w = tid >> 5;
    const int r = lane >> 2, cc = lane & 3;
    const int m0 = (w & 3) * 16, n0 = (w >> 2) * 32;

    const float* sg = sdf + (size_t)b * 64 * 16;
    {
        int row = tid >> 2;
        int kg = (tid & 3) * 4;
        float4 v = *(const float4*)(sg + row * 16 + kg);
        sSF[row * 17 + kg + 0] = v.x;
        sSF[row * 17 + kg + 1] = v.y;
        sSF[row * 17 + kg + 2] = v.z;
        sSF[row * 17 + kg + 3] = v.w;
    }
    if (tid < 192) {
        sp[tid] = point[(size_t)b * 192 + tid];
        sn[tid] = normal[(size_t)b * 192 + tid];
    }
    if (tid < 64)
        scode[tid] = (smask[(size_t)b * 64 + tid] < 0.1f) ? 1.f : 2.f;
    for (int idx = tid; idx < 512; idx += 256)
        scl[idx] = cmask[(size_t)b * 512 + idx];

    const float* dg = dino + (size_t)b * 64 * 384;
    auto load_chunk = [&](int kc, int buf) {
        __half* dst = sDh + buf * 64 * MH_STRIDE;
        const int k0 = kc * 96;
#pragma unroll
        for (int i = 0; i < 6; i++) {
            int idx = tid + i * 256;           // 0..1535
            int row = idx / 24;
            int q = idx % 24;
            float4 v = *(const float4*)(dg + row * 384 + k0 + q * 4);
            __half2 h01 = __floats2half2_rn(v.x, v.y);
            __half2 h23 = __floats2half2_rn(v.z, v.w);
            *(__half2*)(dst + row * MH_STRIDE + q * 4) = h01;
            *(__half2*)(dst + row * MH_STRIDE + q * 4 + 2) = h23;
        }
    };

    float gacc[4][4];
#pragma unroll
    for (int i = 0; i < 4; i++)
#pragma unroll
        for (int j = 0; j < 4; j++) gacc[i][j] = 0.f;

    load_chunk(0, 0);
    __syncthreads();
    for (int c = 0; c < 4; c++) {
        if (c + 1 < 4) load_chunk(c + 1, (c + 1) & 1);
        const __half* buf = sDh + (c & 1) * 64 * MH_STRIDE;
        const __half* aB = buf + (m0 + r) * MH_STRIDE + 2 * cc;
#pragma unroll
        for (int ks = 0; ks < 6; ks++) {
            uint32_t af[4];
            const __half* ap = aB + ks * 16;
            af[0] = *(const uint32_t*)(ap);
            af[1] = *(const uint32_t*)(ap + 8 * MH_STRIDE);
            af[2] = *(const uint32_t*)(ap + 8);
            af[3] = *(const uint32_t*)(ap + 8 * MH_STRIDE + 8);
#pragma unroll
            for (int nt = 0; nt < 4; nt++) {
                const __half* bp = buf + (n0 + nt * 8 + r) * MH_STRIDE + 2 * cc + ks * 16;
                uint32_t bf[2] = { *(const uint32_t*)(bp), *(const uint32_t*)(bp + 8) };
                mma_f16(gacc[nt], af, bf);
            }
        }
        __syncthreads();
    }
#pragma unroll
    for (int nt = 0; nt < 4; nt++) {
        int col = n0 + nt * 8 + 2 * cc;
        int I0 = m0 + r, I1 = I0 + 8;
        sG[I0 * 68 + col]     = gacc[nt][0];
        sG[I0 * 68 + col + 1] = gacc[nt][1];
        sG[I1 * 68 + col]     = gacc[nt][2];
        sG[I1 * 68 + col + 1] = gacc[nt][3];
    }
    __syncthreads();

    if (tid < 64) {
        float nn = fminf(fmaxf(sqrtf(fmaxf(sG[tid * 68 + tid], 0.f)), 1e-20f), 1e10f);
        rnD[tid] = 1.0f / nn;
        float s2 = 0.f;
#pragma unroll
        for (int k = 0; k < 16; k++) { float v = sSF[tid * 17 + k]; s2 += v * v; }
        nn = fminf(fmaxf(sqrtf(s2), 1e-20f), 1e10f);
        rnS[tid] = 1.0f / nn;
    }
    __syncthreads();

    const int tx = tid & 15, ty = tid >> 4;
    float sacc[4][4];
#pragma unroll
    for (int i = 0; i < 4; i++)
#pragma unroll
        for (int j = 0; j < 4; j++) sacc[i][j] = 0.f;
#pragma unroll
    for (int c = 0; c < 16; c++) {
        float aS[4], bS[4];
#pragma unroll
        for (int i = 0; i < 4; i++) aS[i] = sSF[(ty * 4 + i) * 17 + c];
#pragma unroll
        for (int j = 0; j < 4; j++) bS[j] = sSF[(tx * 4 + j) * 17 + c];
#pragma unroll
        for (int i = 0; i < 4; i++)
#pragma unroll
            for (int j = 0; j < 4; j++)
                sacc[i][j] += aS[i] * bS[j];
    }

    float* mrow = mout + (size_t)b * 4096;
#pragma unroll
    for (int i = 0; i < 4; i++) {
        int I = ty * 4 + i;
        float res[4];
#pragma unroll
        for (int j = 0; j < 4; j++) {
            int J = tx * 4 + j;
            float dmap = fminf(fmaxf(sG[I * 68 + J] * rnD[I] * rnD[J], 0.f), 1e10f);
            float smap = 1.f - fminf(fmaxf(sacc[i][j] * rnS[I] * rnS[J], 0.f), 1.f);
            float P1 = 0.f, P2 = 0.f;
#pragma unroll
            for (int d = 0; d < 3; d++) {
                float diff = sp[I * 3 + d] - sp[J * 3 + d];
                P1 += diff * sn[I * 3 + d];
                P2 += diff * sn[J * 3 + d];
            }
            float plane = expf(-0.5f * (fabsf(P1) + fabsf(P2)));
            float mm = (scode[I] * scode[J] == 2.f) ? 1.f : 0.2f;
            float ccv = 0.f;
#pragma unroll
            for (int c = 0; c < 8; c++) ccv += scl[I * 8 + c] * scl[J * 8 + c];
            res[j] = dmap * smap * plane * ccv * mm;
        }
        *(float4*)(mrow + I * 64 + tx * 4) = make_float4(res[0], res[1], res[2], res[3]);
    }
}

// =====================================================================
// Attention kernel v2: 2 heads/iter, warp = (head, m16-tile),
// register softmax, P kept in registers, V via ldmatrix.trans
// =====================================================================
#define AT_Q 0
#define AT_K (AT_Q + 2*64*72*2)
#define AT_V (AT_K + 2*64*72*2)
#define AT_M (AT_V + 2*64*72*2)          // f32 [64][68]
#define AT_B (AT_M + 64*68*4)            // half [1800]
#define SMEM_ATTN_BYTES (AT_B + 1800*2)  // 76304

__global__ __launch_bounds__(256)
void attn_kernel(const float* __restrict__ mult, const float* __restrict__ rel_table,
                 const __half* __restrict__ qkv, __half* __restrict__ obuf)
{
    extern __shared__ char smc[];
    __half* qB     = (__half*)(smc + AT_Q);   // [2][64][72]
    __half* kB     = (__half*)(smc + AT_K);   // [2][64][72]
    __half* vB     = (__half*)(smc + AT_V);   // [2][64][72] natural
    float*  sMult  = (float*) (smc + AT_M);   // [64][68]
    __half* sBiasH = (__half*)(smc + AT_B);   // [1800]

    const int b = blockIdx.x;
    const int tid = threadIdx.x;
    const int lane = tid & 31, w = tid >> 5;
    const int r = lane >> 2, cc = lane & 3;
    const int hs = w >> 2;            // which head of the pair (0/1)
    const int m0 = (w & 3) * 16;      // row tile

    for (int idx = tid; idx < 1024; idx += 256) {
        int row = idx >> 4;
        int c4 = (idx & 15) * 4;
        float4 v = *(const float4*)(mult + (size_t)b * 4096 + row * 64 + c4);
        *(float4*)(sMult + row * 68 + c4) = v;
    }
    for (int i = tid; i < 1800; i += 256)
        sBiasH[i] = __float2half(rel_table[i]);

    const __half* qbase = qkv + (size_t)(b * 64) * 1536;
    const uint32_t vu = smem_u32(vB) + (lane & 15) * 144;   // per-lane ldmatrix base

    for (int hp = 0; hp < 4; hp++) {
        const int h = hp * 2 + hs;
        // load q,k,v for heads 2hp and 2hp+1
        for (int idx = tid; idx < 2048; idx += 256) {
            int hh = idx >> 10;
            int rem = idx & 1023;
            int row = rem >> 4;
            int dg = (rem & 15) * 4;
            const __half* src = qbase + (size_t)row * 1536 + (hp * 2 + hh) * 64 + dg;
            *(uint2*)(qB + hh * 4608 + row * 72 + dg) = *(const uint2*)(src);
            *(uint2*)(kB + hh * 4608 + row * 72 + dg) = *(const uint2*)(src + 512);
            *(uint2*)(vB + hh * 4608 + row * 72 + dg) = *(const uint2*)(src + 1024);
        }
        __syncthreads();

        const __half* qh = qB + hs * 4608;
        const __half* kh = kB + hs * 4608;

        // ---- S = q @ k^T  (16 rows x 64 cols per warp) ----
        float acc[8][4];
#pragma unroll
        for (int nt = 0; nt < 8; nt++)
#pragma unroll
            for (int e = 0; e < 4; e++) acc[nt][e] = 0.f;
        {
            const __half* ap0 = qh + (m0 + r) * 72 + 2 * cc;
#pragma unroll
            for (int kt = 0; kt < 4; kt++) {
                uint32_t af[4];
                const __half* ap = ap0 + kt * 16;
                af[0] = *(const uint32_t*)(ap);
                af[1] = *(const uint32_t*)(ap + 8 * 72);
                af[2] = *(const uint32_t*)(ap + 8);
                af[3] = *(const uint32_t*)(ap + 8 * 72 + 8);
#pragma unroll
                for (int nt = 0; nt < 8; nt++) {
                    const __half* bp = kh + (nt * 8 + r) * 72 + 2 * cc + kt * 16;
                    uint32_t bf[2] = { *(const uint32_t*)(bp), *(const uint32_t*)(bp + 8) };
                    mma_f16(acc[nt], af, bf);
                }
            }
        }

        // ---- logits = s*mult + bias (fp32, in registers) ----
        const int I0 = m0 + r, I1 = I0 + 8;
#pragma unroll
        for (int nt = 0; nt < 8; nt++) {
            int J = nt * 8 + 2 * cc;
            float2 mv0 = *(const float2*)(sMult + I0 * 68 + J);
            float2 mv1 = *(const float2*)(sMult + I1 * 68 + J);
            int dy0 = (I0 >> 3), dy1 = (I1 >> 3);
            int jy = (J >> 3);
            int dxa = (I0 & 7) - (J & 7) + 7;      // J and J+1 share (J>>3); (J&7)+1 ok since J even, (J&7)<=6
            acc[nt][0] = acc[nt][0] * mv0.x + __half2float(sBiasH[((dy0 - jy + 7) * 15 + dxa) * 8 + h]);
            acc[nt][1] = acc[nt][1] * mv0.y + __half2float(sBiasH[((dy0 - jy + 7) * 15 + dxa - 1) * 8 + h]);
            acc[nt][2] = acc[nt][2] * mv1.x + __half2float(sBiasH[((dy1 - jy + 7) * 15 + dxa) * 8 + h]);
            acc[nt][3] = acc[nt][3] * mv1.y + __half2float(sBiasH[((dy1 - jy + 7) * 15 + dxa - 1) * 8 + h]);
        }

        // ---- register softmax over rows I0, I1 ----
        float mx0 = -1e30f, mx1 = -1e30f;
#pragma unroll
        for (int nt = 0; nt < 8; nt++) {
            mx0 = fmaxf(mx0, fmaxf(acc[nt][0], acc[nt][1]));
            mx1 = fmaxf(mx1, fmaxf(acc[nt][2], acc[nt][3]));
        }
        mx0 = fmaxf(mx0, __shfl_xor_sync(0xffffffffu, mx0, 1));
        mx0 = fmaxf(mx0, __shfl_xor_sync(0xffffffffu, mx0, 2));
        mx1 = fmaxf(mx1, __shfl_xor_sync(0xffffffffu, mx1, 1));
        mx1 = fmaxf(mx1, __shfl_xor_sync(0xffffffffu, mx1, 2));
        float s0 = 0.f, s1 = 0.f;
#pragma unroll
        for (int nt = 0; nt < 8; nt++) {
            acc[nt][0] = expf(acc[nt][0] - mx0); s0 += acc[nt][0];
            acc[nt][1] = expf(acc[nt][1] - mx0); s0 += acc[nt][1];
            acc[nt][2] = expf(acc[nt][2] - mx1); s1 += acc[nt][2];
            acc[nt][3] = expf(acc[nt][3] - mx1); s1 += acc[nt][3];
        }
        s0 += __shfl_xor_sync(0xffffffffu, s0, 1);
        s0 += __shfl_xor_sync(0xffffffffu, s0, 2);
        s1 += __shfl_xor_sync(0xffffffffu, s1, 1);
        s1 += __shfl_xor_sync(0xffffffffu, s1, 2);
        const float inv0 = 1.0f / s0, inv1 = 1.0f / s1;

        // ---- pack P into mma A-fragments (half) ----
        uint32_t pa[4][4];
#pragma unroll
        for (int kt = 0; kt < 4; kt++) {
            __half2 h0 = __floats2half2_rn(acc[2 * kt][0] * inv0, acc[2 * kt][1] * inv0);
            __half2 h1 = __floats2half2_rn(acc[2 * kt][2] * inv1, acc[2 * kt][3] * inv1);
            __half2 h2 = __floats2half2_rn(acc[2 * kt + 1][0] * inv0, acc[2 * kt + 1][1] * inv0);
            __half2 h3 = __floats2half2_rn(acc[2 * kt + 1][2] * inv1, acc[2 * kt + 1][3] * inv1);
            pa[kt][0] = *(uint32_t*)&h0;
            pa[kt][1] = *(uint32_t*)&h1;
            pa[kt][2] = *(uint32_t*)&h2;
            pa[kt][3] = *(uint32_t*)&h3;
        }

        // ---- O = P @ V  (V natural in smem; B-frags via ldmatrix.trans) ----
        float oacc[8][4];
#pragma unroll
        for (int nt = 0; nt < 8; nt++)
#pragma unroll
            for (int e = 0; e < 4; e++) oacc[nt][e] = 0.f;
        {
            const uint32_t vb0 = vu + hs * 9216;
#pragma unroll
            for (int kt = 0; kt < 4; kt++) {
#pragma unroll
                for (int nt = 0; nt < 8; nt++) {
                    uint32_t b0, b1;
                    LDSM_X2T(b0, b1, vb0 + kt * 2304 + nt * 16);
                    uint32_t bf[2] = { b0, b1 };
                    mma_f16(oacc[nt], pa[kt], bf);
                }
            }
        }

        // ---- store O (half) ----
        __half* ob = obuf + (size_t)(b * 64) * 512 + h * 64;
#pragma unroll
        for (int nt = 0; nt < 8; nt++) {
            int col = nt * 8 + 2 * cc;
            *(__half2*)(ob + (size_t)I0 * 512 + col) =
                __floats2half2_rn(oacc[nt][0], oacc[nt][1]);
            *(__half2*)(ob + (size_t)I1 * 512 + col) =
                __floats2half2_rn(oacc[nt][2], oacc[nt][3]);
        }
        __syncthreads();
    }
}

// =====================================================================
extern "C" void kernel_launch(void* const* d_in, const int* in_sizes, int n_in,
                              void* d_out, int out_size)
{
    const float* x      = (const float*)d_in[0];
    const float* dino   = (const float*)d_in[1];
    const float* point  = (const float*)d_in[2];
    /* d_in[3] color_feature: unused by reference */
    const float* sdf    = (const float*)d_in[4];
    const float* normal = (const float*)d_in[5];
    const float* smask  = (const float*)d_in[6];
    const float* cmask  = (const float*)d_in[7];
    const float* wq     = (const float*)d_in[8];
    const float* bq     = (const float*)d_in[9];
    const float* wkv    = (const float*)d_in[10];
    const float* bkv    = (const float*)d_in[11];
    const float* rel    = (const float*)d_in[12];
    const float* wproj  = (const float*)d_in[13];
    const float* bproj  = (const float*)d_in[14];
    float* out = (float*)d_out;

    __half *qkvh, *oh, *xh, *wh;
    float *mbuf, *gb;
    cudaGetSymbolAddress((void**)&qkvh, g_qkvh);
    cudaGetSymbolAddress((void**)&mbuf, g_mult);
    cudaGetSymbolAddress((void**)&oh, g_oh);
    cudaGetSymbolAddress((void**)&xh, g_xh);
    cudaGetSymbolAddress((void**)&wh, g_wh);
    cudaGetSymbolAddress((void**)&gb, g_bias);

    cudaFuncSetAttribute(mult_kernel, cudaFuncAttributeMaxDynamicSharedMemorySize, SMEM_MULT_BYTES);
    cudaFuncSetAttribute(attn_kernel, cudaFuncAttributeMaxDynamicSharedMemorySize, SMEM_ATTN_BYTES);
    cudaFuncSetAttribute(gemm_f16<1>, cudaFuncAttributeMaxDynamicSharedMemorySize, SMEM_GEMM_BYTES);
    cudaFuncSetAttribute(gemm_f16<0>, cudaFuncAttributeMaxDynamicSharedMemorySize, SMEM_GEMM_BYTES);

    dim3 blk(256);

    // fp16 conversion: x and weights (SCALE folded into wq/bq)
    conv_kernel<<<1184, 256>>>(x, xh, (MROWS * DIM) / 4, 1.0f);
    conv_kernel<<<128, 256>>>(wq, wh, (512 * 512) / 4, SCALE);
    conv_kernel<<<128, 256>>>(wkv, wh + 512 * 512, (1024 * 512) / 4, 1.0f);
    conv_kernel<<<128, 256>>>(wproj, wh + 1536 * 512, (512 * 512) / 4, 1.0f);
    bias_combine<<<6, 256>>>(bq, bkv, gb);

    // qkv = x @ [SCALE*wq | wkv]^T + [SCALE*bq | bkv]  (half out)
    gemm_f16<1><<<dim3(6, MROWS / 128), blk, SMEM_GEMM_BYTES>>>(
        xh, wh, gb, qkvh, 1536);
    // correlation maps
    mult_kernel<<<NB, blk, SMEM_MULT_BYTES>>>(dino, point, sdf, normal, smask, cmask, mbuf);
    // attention (half in, half out)
    attn_kernel<<<NB, blk, SMEM_ATTN_BYTES>>>(mbuf, rel, qkvh, oh);
    // out = o @ wproj^T + bproj  (float out)
    gemm_f16<0><<<dim3(2, MROWS / 128), blk, SMEM_GEMM_BYTES>>>(
        oh, wh + 1536 * 512, bproj, out, 512);
}

// round 8
// speedup vs baseline: 5.2255x; 1.0677x over previous
#include <cuda_runtime.h>
#include <cuda_fp16.h>
#include <math.h>
#include <stdint.h>

#define NTOK 64
#define DIM 512
#define HEADS 8
#define NB 2048
#define MROWS (NB * NTOK)   // 131072
#define SCALE 0.125f
#define KDIM 512

// ---------------- scratch (device globals; no allocation) ----------------
static __device__ __half g_qkvh[(size_t)MROWS * 1536];  // q(scaled)|k|v  (half)
static __device__ float  g_mult[(size_t)NB * NTOK * NTOK];
static __device__ __half g_oh[(size_t)MROWS * DIM];     // attn out (half)
static __device__ __half g_xh[(size_t)MROWS * DIM];     // x  (half)
static __device__ __half g_wh[(size_t)2048 * 512];      // wq*SCALE|wkv|wproj (half)
static __device__ float  g_bias[1536];                  // SCALE*bq | bkv

__device__ __forceinline__ uint32_t smem_u32(const void* p) {
    uint32_t a;
    asm("{ .reg .u64 t; cvta.to.shared.u64 t, %1; cvt.u32.u64 %0, t; }" : "=r"(a) : "l"(p));
    return a;
}
#define CP_ASYNC16(dst, src) \
    asm volatile("cp.async.cg.shared.global [%0], [%1], 16;" :: "r"(dst), "l"(src) : "memory")
#define CP_COMMIT() asm volatile("cp.async.commit_group;" ::: "memory")
#define CP_WAIT2()  asm volatile("cp.async.wait_group 2;" ::: "memory")
#define CP_WAIT0()  asm volatile("cp.async.wait_group 0;" ::: "memory")

#define LDSM_X4(r0, r1, r2, r3, a) \
    asm volatile("ldmatrix.sync.aligned.m8n8.x4.shared.b16 {%0,%1,%2,%3}, [%4];" \
                 : "=r"(r0), "=r"(r1), "=r"(r2), "=r"(r3) : "r"(a))
#define LDSM_X2T(r0, r1, a) \
    asm volatile("ldmatrix.sync.aligned.m8n8.x2.trans.shared.b16 {%0,%1}, [%2];" \
                 : "=r"(r0), "=r"(r1) : "r"(a))

__device__ __forceinline__ void mma_f16(float* d, const uint32_t* a, const uint32_t* b) {
    asm volatile(
        "mma.sync.aligned.m16n8k16.row.col.f32.f16.f16.f32 "
        "{%0,%1,%2,%3}, {%4,%5,%6,%7}, {%8,%9}, {%0,%1,%2,%3};"
        : "+f"(d[0]), "+f"(d[1]), "+f"(d[2]), "+f"(d[3])
        : "r"(a[0]), "r"(a[1]), "r"(a[2]), "r"(a[3]), "r"(b[0]), "r"(b[1]));
}

// ===================== conversions =====================
__global__ void conv_kernel(const float* __restrict__ in, __half* __restrict__ out, int n4)
{
    int i = blockIdx.x * blockDim.x + threadIdx.x;
    int stride = gridDim.x * blockDim.x;
    for (; i < n4; i += stride) {
        float4 v = ((const float4*)in)[i];
        __half2* o = (__half2*)out;
        o[2 * i]     = __floats2half2_rn(v.x, v.y);
        o[2 * i + 1] = __floats2half2_rn(v.z, v.w);
    }
}

// all weights + bias in one launch. 262144 float4 total.
__global__ void wconv_kernel(const float* __restrict__ wq, const float* __restrict__ wkv,
                             const float* __restrict__ wproj, const float* __restrict__ bq,
                             const float* __restrict__ bkv, float* __restrict__ gb,
                             __half* __restrict__ wh)
{
    int i = blockIdx.x * blockDim.x + threadIdx.x;
    float s = 1.0f;
    const float* src;
    int o;
    if (i < 65536)       { src = wq;    o = i;          s = SCALE; }
    else if (i < 196608) { src = wkv;   o = i - 65536; }
    else                 { src = wproj; o = i - 196608; }
    float4 v = ((const float4*)src)[o];
    __half2* out = (__half2*)wh;
    out[2 * i]     = __floats2half2_rn(v.x * s, v.y * s);
    out[2 * i + 1] = __floats2half2_rn(v.z * s, v.w * s);
    if (i < 384) {
        float4 bv;
        if (i < 128) {
            bv = ((const float4*)bq)[i];
            bv.x *= SCALE; bv.y *= SCALE; bv.z *= SCALE; bv.w *= SCALE;
        } else {
            bv = ((const float4*)bkv)[i - 128];
        }
        ((float4*)gb)[i] = bv;
    }
}

// =====================================================================
// fp16 mma GEMM with ldmatrix fragment loads: C = A @ B^T + bias
// CTA 128x256, 8 warps (2m x 4n) of 64x64; BK=64 halfs; 3-stage cp.async
// =====================================================================
#define BKH 64
#define HSTRIDE 72
#define STAGE_HALFS ((128 + 256) * HSTRIDE)
#define STAGE_BYTES (STAGE_HALFS * 2)
#define NSTAGE 3
#define SMEM_GEMM_BYTES (NSTAGE * STAGE_BYTES)
#define NCHUNK (KDIM / BKH)

template<int OUTH>
__global__ __launch_bounds__(256, 1)
void gemm_f16(const __half* __restrict__ A, const __half* __restrict__ B,
              const float* __restrict__ bias, void* __restrict__ Cv, long ldc)
{
    extern __shared__ char smc[];
    __half* smh = (__half*)smc;
    const int tid = threadIdx.x;
    const int lane = tid & 31;
    const int wid = tid >> 5;
    const int warp_m = wid & 1;
    const int warp_n = wid >> 1;
    const long m0 = (long)blockIdx.y * 128;
    const long n0 = (long)blockIdx.x * 256;

    const __half* Ag = A + m0 * KDIM;
    const __half* Bg = B + n0 * KDIM;
    const uint32_t sb = smem_u32(smc);

    auto copy_chunk = [&](int chunk, int s) {
        const int k0 = chunk * BKH;
        const uint32_t dstA = sb + s * STAGE_BYTES;
        const uint32_t dstB = dstA + 128 * HSTRIDE * 2;
#pragma unroll
        for (int i = 0; i < 4; i++) {
            int idx = tid + i * 256;
            int row = idx >> 3, q = idx & 7;
            CP_ASYNC16(dstA + row * (HSTRIDE * 2) + q * 16,
                       Ag + (long)row * KDIM + k0 + q * 8);
        }
#pragma unroll
        for (int i = 0; i < 8; i++) {
            int idx = tid + i * 256;
            int row = idx >> 3, q = idx & 7;
            CP_ASYNC16(dstB + row * (HSTRIDE * 2) + q * 16,
                       Bg + (long)row * KDIM + k0 + q * 8);
        }
        CP_COMMIT();
    };

    float acc[4][8][4];
#pragma unroll
    for (int mt = 0; mt < 4; mt++)
#pragma unroll
        for (int nt = 0; nt < 8; nt++)
#pragma unroll
            for (int e = 0; e < 4; e++) acc[mt][nt][e] = 0.f;

    copy_chunk(0, 0);
    copy_chunk(1, 1);
    copy_chunk(2, 2);

    const int r = lane >> 2;
    const int cc = lane & 3;
    // per-lane ldmatrix base offsets (within a stage)
    const uint32_t aOff = ((warp_m * 64 + (lane & 15)) * HSTRIDE) * 2 + (lane >> 4) * 16;
    const uint32_t bOff = 128 * HSTRIDE * 2 +
        ((warp_n * 64 + ((lane >> 4) << 3) + (lane & 7)) * HSTRIDE) * 2 + ((lane >> 3) & 1) * 16;

    for (int c = 0; c < NCHUNK; c++) {
        const int s = c % NSTAGE;
        CP_WAIT2();
        __syncthreads();
        const uint32_t stA = sb + s * STAGE_BYTES;
        const uint32_t aL = stA + aOff;
        const uint32_t bL = stA + bOff;

#pragma unroll
        for (int k16 = 0; k16 < 4; k16++) {
            uint32_t af[4][4], bf[8][2];
#pragma unroll
            for (int mt = 0; mt < 4; mt++)
                LDSM_X4(af[mt][0], af[mt][1], af[mt][2], af[mt][3],
                        aL + mt * 16 * HSTRIDE * 2 + k16 * 32);
#pragma unroll
            for (int p = 0; p < 4; p++) {
                uint32_t r0, r1, r2, r3;
                LDSM_X4(r0, r1, r2, r3, bL + p * 16 * HSTRIDE * 2 + k16 * 32);
                bf[2 * p][0] = r0;     bf[2 * p][1] = r1;
                bf[2 * p + 1][0] = r2; bf[2 * p + 1][1] = r3;
            }
#pragma unroll
            for (int mt = 0; mt < 4; mt++)
#pragma unroll
                for (int nt = 0; nt < 8; nt++)
                    mma_f16(acc[mt][nt], af[mt], bf[nt]);
        }
        __syncthreads();
        if (c + 3 < NCHUNK) copy_chunk(c + 3, s);
        else CP_COMMIT();
    }

    if (OUTH) {
        __half* se = smh;
        const int row0 = warp_m * 64;
        const int col0 = warp_n * 64;
#pragma unroll
        for (int mt = 0; mt < 4; mt++)
#pragma unroll
            for (int nt = 0; nt < 8; nt++) {
                int rr = row0 + mt * 16 + r;
                int cb = col0 + nt * 8 + 2 * cc;
                float2 bv = *(const float2*)(bias + n0 + cb);
                *(__half2*)(se + rr * 264 + cb) =
                    __floats2half2_rn(acc[mt][nt][0] + bv.x, acc[mt][nt][1] + bv.y);
                *(__half2*)(se + (rr + 8) * 264 + cb) =
                    __floats2half2_rn(acc[mt][nt][2] + bv.x, acc[mt][nt][3] + bv.y);
            }
        __syncthreads();
        __half* Ch = (__half*)Cv;
#pragma unroll
        for (int i = 0; i < 16; i++) {
            int idx = tid + i * 256;
            int row = idx >> 5;
            int c8 = (idx & 31) * 8;
            float4 v = *(const float4*)(se + row * 264 + c8);
            *(float4*)(Ch + (m0 + row) * ldc + n0 + c8) = v;
        }
    } else {
        float* se = (float*)smc;
        const int row0 = warp_m * 64;
        const int col0 = warp_n * 64;
#pragma unroll
        for (int mt = 0; mt < 4; mt++)
#pragma unroll
            for (int nt = 0; nt < 8; nt++) {
                int rr = row0 + mt * 16 + r;
                int cb = col0 + nt * 8 + 2 * cc;
                float2 bv = *(const float2*)(bias + n0 + cb);
                *(float2*)(se + rr * 264 + cb) =
                    make_float2(acc[mt][nt][0] + bv.x, acc[mt][nt][1] + bv.y);
                *(float2*)(se + (rr + 8) * 264 + cb) =
                    make_float2(acc[mt][nt][2] + bv.x, acc[mt][nt][3] + bv.y);
            }
        __syncthreads();
        float* Cf = (float*)Cv;
#pragma unroll
        for (int i = 0; i < 32; i++) {
            int idx = tid + i * 256;
            int row = idx >> 6;
            int c4 = (idx & 63) * 4;
            float4 v = *(const float4*)(se + row * 264 + c4);
            *(float4*)(Cf + (m0 + row) * ldc + n0 + c4) = v;
        }
    }
}

// =====================================================================
// Correlation-map kernel: ALL THREE Grams (dino / sdf / cluster) via fp16 mma
// =====================================================================
#define MH_STRIDE 104
#define MK_D   0                       // half [2][64][104] = 26624 B; later overlaid by sG3
#define MK_G   (MK_D + 26624)          // float [64][68]
#define MK_G2  (MK_G + 17408)          // float [64][68]
#define MK_SF  (MK_G2 + 17408)         // half [64][24]  sdf
#define MK_SCL (MK_SF + 3072)          // half [64][24]  cluster (k8-15 zero)
#define MK_RND (MK_SCL + 3072)
#define MK_RNS (MK_RND + 256)
#define MK_SP  (MK_RNS + 256)
#define MK_SN  (MK_SP + 768)
#define MK_SC  (MK_SN + 768)
#define SMEM_MULT_BYTES (MK_SC + 256)  // 69888

__global__ __launch_bounds__(256)
void mult_kernel(const float* __restrict__ dino, const float* __restrict__ point,
                 const float* __restrict__ sdf, const float* __restrict__ normal,
                 const float* __restrict__ smask, const float* __restrict__ cmask,
                 float* __restrict__ mout)
{
    extern __shared__ char smc[];
    __half* sDh  = (__half*)(smc + MK_D);
    float* sG3   = (float*)(smc + MK_D);    // overlays sDh after dino loop
    float* sG    = (float*)(smc + MK_G);
    float* sG2   = (float*)(smc + MK_G2);
    __half* sfh  = (__half*)(smc + MK_SF);
    __half* sclh = (__half*)(smc + MK_SCL);
    float* rnD   = (float*)(smc + MK_RND);
    float* rnS   = (float*)(smc + MK_RNS);
    float* sp    = (float*)(smc + MK_SP);
    float* sn    = (float*)(smc + MK_SN);
    float* scode = (float*)(smc + MK_SC);

    const int b = blockIdx.x;
    const int tid = threadIdx.x;
    const int lane = tid & 31, w = tid >> 5;
    const int r = lane >> 2, cc = lane & 3;
    const int m0 = (w & 3) * 16, n0 = (w >> 2) * 32;

    // sdf -> half [64][24]
    {
        int row = tid >> 2;
        int kg = (tid & 3) * 4;
        float4 v = *(const float4*)(sdf + (size_t)b * 1024 + row * 16 + kg);
        *(__half2*)(sfh + row * 24 + kg)     = __floats2half2_rn(v.x, v.y);
        *(__half2*)(sfh + row * 24 + kg + 2) = __floats2half2_rn(v.z, v.w);
    }
    // cluster -> half [64][24], k8..15 zeroed
    if (tid < 128) {
        int row = tid >> 1;
        int c4 = (tid & 1) * 4;
        float4 v = *(const float4*)(cmask + (size_t)b * 512 + row * 8 + c4);
        *(__half2*)(sclh + row * 24 + c4)     = __floats2half2_rn(v.x, v.y);
        *(__half2*)(sclh + row * 24 + c4 + 2) = __floats2half2_rn(v.z, v.w);
        *(uint2*)(sclh + row * 24 + 8 + c4) = make_uint2(0u, 0u);
    }
    if (tid < 192) {
        sp[tid] = point[(size_t)b * 192 + tid];
        sn[tid] = normal[(size_t)b * 192 + tid];
    }
    if (tid < 64)
        scode[tid] = (smask[(size_t)b * 64 + tid] < 0.1f) ? 1.f : 2.f;

    const float* dg = dino + (size_t)b * 64 * 384;
    auto load_chunk = [&](int kc, int buf) {
        __half* dst = sDh + buf * 64 * MH_STRIDE;
        const int k0 = kc * 96;
#pragma unroll
        for (int i = 0; i < 6; i++) {
            int idx = tid + i * 256;
            int row = idx / 24;
            int q = idx % 24;
            float4 v = *(const float4*)(dg + row * 384 + k0 + q * 4);
            *(__half2*)(dst + row * MH_STRIDE + q * 4)     = __floats2half2_rn(v.x, v.y);
            *(__half2*)(dst + row * MH_STRIDE + q * 4 + 2) = __floats2half2_rn(v.z, v.w);
        }
    };

    float gacc[4][4];
#pragma unroll
    for (int i = 0; i < 4; i++)
#pragma unroll
        for (int j = 0; j < 4; j++) gacc[i][j] = 0.f;

    load_chunk(0, 0);
    __syncthreads();
    for (int c = 0; c < 4; c++) {
        if (c + 1 < 4) load_chunk(c + 1, (c + 1) & 1);
        const __half* buf = sDh + (c & 1) * 64 * MH_STRIDE;
        const __half* aB = buf + (m0 + r) * MH_STRIDE + 2 * cc;
#pragma unroll
        for (int ks = 0; ks < 6; ks++) {
            uint32_t af[4];
            const __half* ap = aB + ks * 16;
            af[0] = *(const uint32_t*)(ap);
            af[1] = *(const uint32_t*)(ap + 8 * MH_STRIDE);
            af[2] = *(const uint32_t*)(ap + 8);
            af[3] = *(const uint32_t*)(ap + 8 * MH_STRIDE + 8);
#pragma unroll
            for (int nt = 0; nt < 4; nt++) {
                const __half* bp = buf + (n0 + nt * 8 + r) * MH_STRIDE + 2 * cc + ks * 16;
                uint32_t bf[2] = { *(const uint32_t*)(bp), *(const uint32_t*)(bp + 8) };
                mma_f16(gacc[nt], af, bf);
            }
        }
        __syncthreads();
    }

    // sdf + cluster Grams: one k16 step each
    float s2[4][4], s3[4][4];
#pragma unroll
    for (int i = 0; i < 4; i++)
#pragma unroll
        for (int j = 0; j < 4; j++) { s2[i][j] = 0.f; s3[i][j] = 0.f; }
    {
        const __half* ap2 = sfh + (m0 + r) * 24 + 2 * cc;
        uint32_t af2[4] = { *(const uint32_t*)(ap2), *(const uint32_t*)(ap2 + 8 * 24),
                            *(const uint32_t*)(ap2 + 8), *(const uint32_t*)(ap2 + 8 * 24 + 8) };
        const __half* ap3 = sclh + (m0 + r) * 24 + 2 * cc;
        uint32_t af3[4] = { *(const uint32_t*)(ap3), *(const uint32_t*)(ap3 + 8 * 24),
                            *(const uint32_t*)(ap3 + 8), *(const uint32_t*)(ap3 + 8 * 24 + 8) };
#pragma unroll
        for (int nt = 0; nt < 4; nt++) {
            const __half* bp2 = sfh + (n0 + nt * 8 + r) * 24 + 2 * cc;
            uint32_t bf2[2] = { *(const uint32_t*)(bp2), *(const uint32_t*)(bp2 + 8) };
            mma_f16(s2[nt], af2, bf2);
            const __half* bp3 = sclh + (n0 + nt * 8 + r) * 24 + 2 * cc;
            uint32_t bf3[2] = { *(const uint32_t*)(bp3), *(const uint32_t*)(bp3 + 8) };
            mma_f16(s3[nt], af3, bf3);
        }
    }

    // write all Gram fragments (sG3 overlays sDh — all dino reads done)
#pragma unroll
    for (int nt = 0; nt < 4; nt++) {
        int col = n0 + nt * 8 + 2 * cc;
        int I0 = m0 + r, I1 = I0 + 8;
        sG[I0 * 68 + col]      = gacc[nt][0];
        sG[I0 * 68 + col + 1]  = gacc[nt][1];
        sG[I1 * 68 + col]      = gacc[nt][2];
        sG[I1 * 68 + col + 1]  = gacc[nt][3];
        sG2[I0 * 68 + col]     = s2[nt][0];
        sG2[I0 * 68 + col + 1] = s2[nt][1];
        sG2[I1 * 68 + col]     = s2[nt][2];
        sG2[I1 * 68 + col + 1] = s2[nt][3];
        sG3[I0 * 68 + col]     = s3[nt][0];
        sG3[I0 * 68 + col + 1] = s3[nt][1];
        sG3[I1 * 68 + col]     = s3[nt][2];
        sG3[I1 * 68 + col + 1] = s3[nt][3];
    }
    __syncthreads();

    if (tid < 64) {
        float nn = fminf(fmaxf(sqrtf(fmaxf(sG[tid * 68 + tid], 0.f)), 1e-20f), 1e10f);
        rnD[tid] = 1.0f / nn;
        nn = fminf(fmaxf(sqrtf(fmaxf(sG2[tid * 68 + tid], 0.f)), 1e-20f), 1e10f);
        rnS[tid] = 1.0f / nn;
    }
    __syncthreads();

    const int tx = tid & 15, ty = tid >> 4;
    float* mrow = mout + (size_t)b * 4096;
#pragma unroll
    for (int i = 0; i < 4; i++) {
        int I = ty * 4 + i;
        float ga[4], g2a[4], g3a[4], res[4];
        *(float4*)ga  = *(const float4*)(sG  + I * 68 + tx * 4);
        *(float4*)g2a = *(const float4*)(sG2 + I * 68 + tx * 4);
        *(float4*)g3a = *(const float4*)(sG3 + I * 68 + tx * 4);
#pragma unroll
        for (int j = 0; j < 4; j++) {
            int J = tx * 4 + j;
            float dmap = fminf(fmaxf(ga[j] * rnD[I] * rnD[J], 0.f), 1e10f);
            float smap = 1.f - fminf(fmaxf(g2a[j] * rnS[I] * rnS[J], 0.f), 1.f);
            float P1 = 0.f, P2 = 0.f;
#pragma unroll
            for (int d = 0; d < 3; d++) {
                float diff = sp[I * 3 + d] - sp[J * 3 + d];
                P1 += diff * sn[I * 3 + d];
                P2 += diff * sn[J * 3 + d];
            }
            float plane = expf(-0.5f * (fabsf(P1) + fabsf(P2)));
            float mm = (scode[I] * scode[J] == 2.f) ? 1.f : 0.2f;
            res[j] = dmap * smap * plane * g3a[j] * mm;
        }
        *(float4*)(mrow + I * 64 + tx * 4) = make_float4(res[0], res[1], res[2], res[3]);
    }
}

// =====================================================================
// Attention kernel: cp.async loads, ldmatrix frags, register softmax,
// smem-staged coalesced O stores
// =====================================================================
#define AT_Q 0
#define AT_K (AT_Q + 2*64*72*2)          // 18432 spacing
#define AT_V (AT_K + 2*64*72*2)
#define AT_M (AT_V + 2*64*72*2)          // f32 [64][68]
#define AT_B (AT_M + 64*68*4)            // half [1800]
#define SMEM_ATTN_BYTES (AT_B + 1800*2)  // 76304

__global__ __launch_bounds__(256)
void attn_kernel(const float* __restrict__ mult, const float* __restrict__ rel_table,
                 const __half* __restrict__ qkv, __half* __restrict__ obuf)
{
    extern __shared__ char smc[];
    __half* qB     = (__half*)(smc + AT_Q);   // [2][64][72]
    __half* vB     = (__half*)(smc + AT_V);   // [2][64][72] natural
    float*  sMult  = (float*) (smc + AT_M);
    __half* sBiasH = (__half*)(smc + AT_B);

    const int b = blockIdx.x;
    const int tid = threadIdx.x;
    const int lane = tid & 31, w = tid >> 5;
    const int r = lane >> 2, cc = lane & 3;
    const int hs = w >> 2;
    const int m0 = (w & 3) * 16;
    const uint32_t sb = smem_u32(smc);

    for (int idx = tid; idx < 1024; idx += 256) {
        int row = idx >> 4;
        int c4 = (idx & 15) * 4;
        float4 v = *(const float4*)(mult + (size_t)b * 4096 + row * 64 + c4);
        *(float4*)(sMult + row * 68 + c4) = v;
    }
    for (int i = tid; i < 1800; i += 256)
        sBiasH[i] = __float2half(rel_table[i]);

    const __half* qbase = qkv + (size_t)(b * 64) * 1536;
    // per-lane ldmatrix bases (head-half fixed per warp)
    const uint32_t qOff = sb + AT_Q + hs * 9216 +
        ((m0 + (lane & 15)) * 72) * 2 + (lane >> 4) * 16;
    const uint32_t kOff = sb + AT_K + hs * 9216 +
        ((((lane >> 4) << 3) + (lane & 7)) * 72) * 2 + ((lane >> 3) & 1) * 16;
    const uint32_t vOff = sb + AT_V + hs * 9216 + (lane & 15) * 144;

    for (int hp = 0; hp < 4; hp++) {
        const int h = hp * 2 + hs;
        // cp.async q,k,v for both heads: 3072 x 16B chunks
#pragma unroll
        for (int i = 0; i < 12; i++) {
            int c = tid + i * 256;
            int tensor = c >> 10;              // 0=q 1=k 2=v
            int rem = c & 1023;
            int hh = rem >> 9;
            int rr = rem & 511;
            int row = rr >> 3;
            int q8 = rr & 7;
            CP_ASYNC16(sb + AT_Q + tensor * 18432 + hh * 9216 + row * 144 + q8 * 16,
                       qbase + (size_t)row * 1536 + (hp * 2 + hh) * 64 + tensor * 512 + q8 * 8);
        }
        CP_COMMIT();
        CP_WAIT0();
        __syncthreads();

        // ---- S = q @ k^T via ldmatrix frags ----
        float acc[8][4];
#pragma unroll
        for (int nt = 0; nt < 8; nt++)
#pragma unroll
            for (int e = 0; e < 4; e++) acc[nt][e] = 0.f;
#pragma unroll
        for (int kt = 0; kt < 4; kt++) {
            uint32_t af[4], bf[8][2];
            LDSM_X4(af[0], af[1], af[2], af[3], qOff + kt * 32);
#pragma unroll
            for (int p = 0; p < 4; p++) {
                uint32_t r0, r1, r2, r3;
                LDSM_X4(r0, r1, r2, r3, kOff + p * 16 * 144 + kt * 32);
                bf[2 * p][0] = r0;     bf[2 * p][1] = r1;
                bf[2 * p + 1][0] = r2; bf[2 * p + 1][1] = r3;
            }
#pragma unroll
            for (int nt = 0; nt < 8; nt++)
                mma_f16(acc[nt], af, bf[nt]);
        }

        // ---- logits = s*mult + bias ----
        const int I0 = m0 + r, I1 = I0 + 8;
#pragma unroll
        for (int nt = 0; nt < 8; nt++) {
            int J = nt * 8 + 2 * cc;
            float2 mv0 = *(const float2*)(sMult + I0 * 68 + J);
            float2 mv1 = *(const float2*)(sMult + I1 * 68 + J);
            int dy0 = (I0 >> 3), dy1 = (I1 >> 3);
            int jy = (J >> 3);
            int dxa = (I0 & 7) - (J & 7) + 7;
            acc[nt][0] = acc[nt][0] * mv0.x + __half2float(sBiasH[((dy0 - jy + 7) * 15 + dxa) * 8 + h]);
            acc[nt][1] = acc[nt][1] * mv0.y + __half2float(sBiasH[((dy0 - jy + 7) * 15 + dxa - 1) * 8 + h]);
            acc[nt][2] = acc[nt][2] * mv1.x + __half2float(sBiasH[((dy1 - jy + 7) * 15 + dxa) * 8 + h]);
            acc[nt][3] = acc[nt][3] * mv1.y + __half2float(sBiasH[((dy1 - jy + 7) * 15 + dxa - 1) * 8 + h]);
        }

        // ---- register softmax ----
        float mx0 = -1e30f, mx1 = -1e30f;
#pragma unroll
        for (int nt = 0; nt < 8; nt++) {
            mx0 = fmaxf(mx0, fmaxf(acc[nt][0], acc[nt][1]));
            mx1 = fmaxf(mx1, fmaxf(acc[nt][2], acc[nt][3]));
        }
        mx0 = fmaxf(mx0, __shfl_xor_sync(0xffffffffu, mx0, 1));
        mx0 = fmaxf(mx0, __shfl_xor_sync(0xffffffffu, mx0, 2));
        mx1 = fmaxf(mx1, __shfl_xor_sync(0xffffffffu, mx1, 1));
        mx1 = fmaxf(mx1, __shfl_xor_sync(0xffffffffu, mx1, 2));
        float s0 = 0.f, s1 = 0.f;
#pragma unroll
        for (int nt = 0; nt < 8; nt++) {
            acc[nt][0] = expf(acc[nt][0] - mx0); s0 += acc[nt][0];
            acc[nt][1] = expf(acc[nt][1] - mx0); s0 += acc[nt][1];
            acc[nt][2] = expf(acc[nt][2] - mx1); s1 += acc[nt][2];
            acc[nt][3] = expf(acc[nt][3] - mx1); s1 += acc[nt][3];
        }
        s0 += __shfl_xor_sync(0xffffffffu, s0, 1);
        s0 += __shfl_xor_sync(0xffffffffu, s0, 2);
        s1 += __shfl_xor_sync(0xffffffffu, s1, 1);
        s1 += __shfl_xor_sync(0xffffffffu, s1, 2);
        const float inv0 = 1.0f / s0, inv1 = 1.0f / s1;

        // ---- pack P into A-fragments ----
        uint32_t pa[4][4];
#pragma unroll
        for (int kt = 0; kt < 4; kt++) {
            __half2 h0 = __floats2half2_rn(acc[2 * kt][0] * inv0, acc[2 * kt][1] * inv0);
            __half2 h1 = __floats2half2_rn(acc[2 * kt][2] * inv1, acc[2 * kt][3] * inv1);
            __half2 h2 = __floats2half2_rn(acc[2 * kt + 1][0] * inv0, acc[2 * kt + 1][1] * inv0);
            __half2 h3 = __floats2half2_rn(acc[2 * kt + 1][2] * inv1, acc[2 * kt + 1][3] * inv1);
            pa[kt][0] = *(uint32_t*)&h0;
            pa[kt][1] = *(uint32_t*)&h1;
            pa[kt][2] = *(uint32_t*)&h2;
            pa[kt][3] = *(uint32_t*)&h3;
        }

        // ---- O = P @ V (V natural, B-frags via ldmatrix.trans) ----
        float oacc[8][4];
#pragma unroll
        for (int nt = 0; nt < 8; nt++)
#pragma unroll
            for (int e = 0; e < 4; e++) oacc[nt][e] = 0.f;
#pragma unroll
        for (int kt = 0; kt < 4; kt++) {
#pragma unroll
            for (int nt = 0; nt < 8; nt++) {
                uint32_t b0, b1;
                LDSM_X2T(b0, b1, vOff + kt * 2304 + nt * 16);
                uint32_t bf[2] = { b0, b1 };
                mma_f16(oacc[nt], pa[kt], bf);
            }
        }

        // ---- stage O into qB (q consumed), then coalesced write ----
        __syncthreads();
        {
            __half* stg = qB + hs * 4608;
#pragma unroll
            for (int nt = 0; nt < 8; nt++) {
                int col = nt * 8 + 2 * cc;
                *(__half2*)(stg + I0 * 72 + col) =
                    __floats2half2_rn(oacc[nt][0], oacc[nt][1]);
                *(__half2*)(stg + I1 * 72 + col) =
                    __floats2half2_rn(oacc[nt][2], oacc[nt][3]);
            }
        }
        __syncthreads();
#pragma unroll
        for (int i = 0; i < 4; i++) {
            int idx = tid + i * 256;          // 0..1023
            int hh = idx >> 9;
            int rem = idx & 511;
            int row = rem >> 3;
            int c8 = (rem & 7) * 8;
            float4 v = *(const float4*)(qB + hh * 4608 + row * 72 + c8);
            *(float4*)(obuf + (size_t)(b * 64 + row) * 512 + (hp * 2 + hh) * 64 + c8) = v;
        }
        __syncthreads();
    }
}

// =====================================================================
extern "C" void kernel_launch(void* const* d_in, const int* in_sizes, int n_in,
                              void* d_out, int out_size)
{
    const float* x      = (const float*)d_in[0];
    const float* dino   = (const float*)d_in[1];
    const float* point  = (const float*)d_in[2];
    /* d_in[3] color_feature: unused by reference */
    const float* sdf    = (const float*)d_in[4];
    const float* normal = (const float*)d_in[5];
    const float* smask  = (const float*)d_in[6];
    const float* cmask  = (const float*)d_in[7];
    const float* wq     = (const float*)d_in[8];
    const float* bq     = (const float*)d_in[9];
    const float* wkv    = (const float*)d_in[10];
    const float* bkv    = (const float*)d_in[11];
    const float* rel    = (const float*)d_in[12];
    const float* wproj  = (const float*)d_in[13];
    const float* bproj  = (const float*)d_in[14];
    float* out = (float*)d_out;

    __half *qkvh, *oh, *xh, *wh;
    float *mbuf, *gb;
    cudaGetSymbolAddress((void**)&qkvh, g_qkvh);
    cudaGetSymbolAddress((void**)&mbuf, g_mult);
    cudaGetSymbolAddress((void**)&oh, g_oh);
    cudaGetSymbolAddress((void**)&xh, g_xh);
    cudaGetSymbolAddress((void**)&wh, g_wh);
    cudaGetSymbolAddress((void**)&gb, g_bias);

    cudaFuncSetAttribute(mult_kernel, cudaFuncAttributeMaxDynamicSharedMemorySize, SMEM_MULT_BYTES);
    cudaFuncSetAttribute(attn_kernel, cudaFuncAttributeMaxDynamicSharedMemorySize, SMEM_ATTN_BYTES);
    cudaFuncSetAttribute(gemm_f16<1>, cudaFuncAttributeMaxDynamicSharedMemorySize, SMEM_GEMM_BYTES);
    cudaFuncSetAttribute(gemm_f16<0>, cudaFuncAttributeMaxDynamicSharedMemorySize, SMEM_GEMM_BYTES);

    dim3 blk(256);

    // conversions
    conv_kernel<<<1184, 256>>>(x, xh, (MROWS * DIM) / 4);
    wconv_kernel<<<1024, 256>>>(wq, wkv, wproj, bq, bkv, gb, wh);

    // qkv = x @ [SCALE*wq | wkv]^T + [SCALE*bq | bkv]  (half out)
    gemm_f16<1><<<dim3(6, MROWS / 128), blk, SMEM_GEMM_BYTES>>>(
        xh, wh, gb, qkvh, 1536);
    // correlation maps
    mult_kernel<<<NB, blk, SMEM_MULT_BYTES>>>(dino, point, sdf, normal, smask, cmask, mbuf);
    // attention (half in, half out)
    attn_kernel<<<NB, blk, SMEM_ATTN_BYTES>>>(mbuf, rel, qkvh, oh);
    // out = o @ wproj^T + bproj  (float out)
    gemm_f16<0><<<dim3(2, MROWS / 128), blk, SMEM_GEMM_BYTES>>>(
        oh, wh + 1536 * 512, bproj, out, 512);
}